// round 5
// baseline (speedup 1.0000x reference)
#include <cuda_runtime.h>
#include <math.h>
#include <stdint.h>

// Problem dims
#define Bc  32
#define Tc  128
#define TYc 64
#define Ec  512
#define Hc  512
#define HHc 256
#define Vc  32000

// ---------------- scratch (__device__ globals; no allocations) ----------------
__device__ float g_xemb  [Bc*Tc*Ec];
__device__ float g_xbemb [Bc*Tc*Ec];
__device__ float g_yemb  [Bc*TYc*Ec];
__device__ int   g_xback [Bc*Tc];
__device__ float g_encpre_f[Bc*Tc*4*HHc];
__device__ float g_encpre_b[Bc*Tc*4*HHc];
__device__ float g_decpre  [Bc*TYc*4*Hc];
__device__ float g_ench[2][2*Bc*HHc];   // ping-pong h state, [dir][b][u]
__device__ float g_encc[2*Bc*HHc];      // c state, in-place
__device__ float g_hiddens[Bc*Tc*Hc];   // [b][t][fwd|bwd]
__device__ float g_hsum[Bc*Hc];
__device__ float g_csum[Bc*Hc];
__device__ float g_dech[2][Bc*Hc];      // ping-pong decoder h
__device__ float g_decc[Bc*Hc];
__device__ float g_outhid[Bc*TYc*2*Hc]; // [b][ty][h|ctx]

__device__ __forceinline__ float sigm(float x) { return 1.f / (1.f + expf(-x)); }

// ======================================================================
// mma.sync tf32 GEMM: C[M,N] = A[M,K] @ W[N,K]^T (+b1[n] +b2[n])
// CTA tile 128x128, 8 warps, warp tile 64x32 (4 m16 x 4 n8 mma tiles).
// K-chunk 16, double-buffered cp.async, static smem (40KB).
// Requires: M%128==0, N%128==0, K%16==0, K>=32.
// Row pitch 20 floats = 80B: 16B-aligned for cp.async, and bank-conflict-free
// for the (lane>>2, lane&3) fragment LDS pattern.
// ======================================================================
#define KC 16
#define PITCH 20

__device__ __forceinline__ void mma_tf32(float* d, const uint32_t* a, const uint32_t* b) {
    asm volatile(
        "mma.sync.aligned.m16n8k8.row.col.f32.tf32.tf32.f32 "
        "{%0,%1,%2,%3}, {%4,%5,%6,%7}, {%8,%9}, {%0,%1,%2,%3};\n"
        : "+f"(d[0]), "+f"(d[1]), "+f"(d[2]), "+f"(d[3])
        : "r"(a[0]), "r"(a[1]), "r"(a[2]), "r"(a[3]), "r"(b[0]), "r"(b[1]));
}

__global__ __launch_bounds__(256, 2)
void k_mma(const float* __restrict__ A, const float* __restrict__ W,
           const float* __restrict__ b1, const float* __restrict__ b2,
           float* __restrict__ C, int M, int N, int K) {
    __shared__ float sA[2][128 * PITCH];
    __shared__ float sB[2][128 * PITCH];

    const int tid  = threadIdx.x;
    const int wid  = tid >> 5;
    const int lane = tid & 31;
    const int g    = lane >> 2;       // group row 0..7
    const int t    = lane & 3;        // k sub-index 0..3
    const int wm   = (wid & 1) * 64;  // warp M offset
    const int wn   = (wid >> 1) * 32; // warp N offset
    const int bm   = blockIdx.x * 128;
    const int bn   = blockIdx.y * 128;

    const float* Ab = A + (size_t)bm * K;
    const float* Wb = W + (size_t)bn * K;

    // each thread copies 2 x 16B for A and 2 x 16B for B per stage
    const int ldrow = tid >> 2;       // 0..63
    const int ldch  = (tid & 3) * 4;  // float offset 0,4,8,12

#define LOAD_STAGE(KC0, S) do { \
    _Pragma("unroll") \
    for (int _i = 0; _i < 2; _i++) { \
        int _r = ldrow + _i * 64; \
        uint32_t _da; \
        asm("{ .reg .u64 t; cvta.to.shared.u64 t, %1; cvt.u32.u64 %0, t; }" \
            : "=r"(_da) : "l"(&sA[S][_r * PITCH + ldch])); \
        const float* _sa = Ab + (size_t)_r * K + (KC0) + ldch; \
        asm volatile("cp.async.cg.shared.global [%0], [%1], 16;" :: "r"(_da), "l"(_sa)); \
        uint32_t _db; \
        asm("{ .reg .u64 t; cvta.to.shared.u64 t, %1; cvt.u32.u64 %0, t; }" \
            : "=r"(_db) : "l"(&sB[S][_r * PITCH + ldch])); \
        const float* _sb = Wb + (size_t)_r * K + (KC0) + ldch; \
        asm volatile("cp.async.cg.shared.global [%0], [%1], 16;" :: "r"(_db), "l"(_sb)); \
    } \
    asm volatile("cp.async.commit_group;" ::: "memory"); \
} while (0)

    float acc[4][4][4];
#pragma unroll
    for (int i = 0; i < 4; i++)
#pragma unroll
        for (int j = 0; j < 4; j++)
#pragma unroll
            for (int r = 0; r < 4; r++) acc[i][j][r] = 0.f;

    const int NS = K / KC;
    LOAD_STAGE(0, 0);
    LOAD_STAGE(KC, 1);

    for (int s = 0; s < NS; s++) {
        if (s + 1 < NS) asm volatile("cp.async.wait_group 1;" ::: "memory");
        else            asm volatile("cp.async.wait_group 0;" ::: "memory");
        __syncthreads();
        const int buf = s & 1;
        const float* pa = &sA[buf][0];
        const float* pb = &sB[buf][0];
#pragma unroll
        for (int ks = 0; ks < 2; ks++) {
            const int kb = ks * 8 + t;
            uint32_t af[4][4], bf[4][2];
#pragma unroll
            for (int mt = 0; mt < 4; mt++) {
                const float* sa = pa + (wm + mt * 16 + g) * PITCH + kb;
                af[mt][0] = __float_as_uint(sa[0]);
                af[mt][1] = __float_as_uint(sa[8 * PITCH]);
                af[mt][2] = __float_as_uint(sa[4]);
                af[mt][3] = __float_as_uint(sa[8 * PITCH + 4]);
            }
#pragma unroll
            for (int nt = 0; nt < 4; nt++) {
                const float* sb = pb + (wn + nt * 8 + g) * PITCH + kb;
                bf[nt][0] = __float_as_uint(sb[0]);
                bf[nt][1] = __float_as_uint(sb[4]);
            }
#pragma unroll
            for (int mt = 0; mt < 4; mt++)
#pragma unroll
                for (int nt = 0; nt < 4; nt++)
                    mma_tf32(acc[mt][nt], af[mt], bf[nt]);
        }
        __syncthreads();
        if (s + 2 < NS) LOAD_STAGE((s + 2) * KC, buf);
    }

    // epilogue: c0=[g][2t], c1=[g][2t+1], c2=[g+8][2t], c3=[g+8][2t+1]
#pragma unroll
    for (int nt = 0; nt < 4; nt++) {
        const int n0 = bn + wn + nt * 8 + 2 * t;
        float bb0 = 0.f, bb1 = 0.f;
        if (b1) { bb0 += b1[n0]; bb1 += b1[n0 + 1]; }
        if (b2) { bb0 += b2[n0]; bb1 += b2[n0 + 1]; }
#pragma unroll
        for (int mt = 0; mt < 4; mt++) {
            const int m0 = bm + wm + mt * 16 + g;
            float2 v0 = make_float2(acc[mt][nt][0] + bb0, acc[mt][nt][1] + bb1);
            float2 v1 = make_float2(acc[mt][nt][2] + bb0, acc[mt][nt][3] + bb1);
            *(float2*)(C + (size_t)m0 * N + n0)       = v0;
            *(float2*)(C + (size_t)(m0 + 8) * N + n0) = v1;
        }
    }
#undef LOAD_STAGE
}

// ---------------- init ----------------
__global__ void k_init() {
    int i = blockIdx.x * blockDim.x + threadIdx.x;
    if (i < Bc*Hc)      { g_hsum[i] = 0.f; g_csum[i] = 0.f; }
    if (i < 2*2*Bc*HHc) (&g_ench[0][0])[i] = 0.f;
    if (i < 2*Bc*HHc)   g_encc[i] = 0.f;
    if (i < Bc*Tc)      g_xback[i] = 0;
}

// ---------------- pad-aware reversed tokens ----------------
__global__ void k_xback(const int* __restrict__ x, const float* __restrict__ mask) {
    int b = threadIdx.x;
    if (b >= Bc) return;
    float s = 0.f;
    for (int t = 0; t < Tc; t++) s += mask[b*Tc + t];
    int pad = Tc - (int)(s + 0.5f);
    for (int j = 0; j < Tc; j++) {
        int r = Tc - 1 - j - pad;
        if (r < 0) r = 0;
        g_xback[b*Tc + r] = x[b*Tc + j];
    }
}

// ---------------- embedding gather ----------------
__global__ void k_gather(const int* __restrict__ idx, const float* __restrict__ embed,
                         float* __restrict__ out) {
    int row = blockIdx.x;
    int e = threadIdx.x;
    const float4* src = (const float4*)embed + (size_t)idx[row] * (Ec/4);
    ((float4*)out)[(size_t)row * (Ec/4) + e] = src[e];
}

// ---------------- encoder step ----------------
__global__ __launch_bounds__(256, 1)
void k_enc_step(int t, const float* __restrict__ whh_f, const float* __restrict__ whh_b) {
    const int dir = blockIdx.y;
    const int u0 = blockIdx.x * 8;
    const float* whh = dir ? whh_b : whh_f;
    const float* pre = dir ? g_encpre_b : g_encpre_f;
    float* cst = g_encc + dir * (Bc*HHc);
    const float* h_in = g_ench[t & 1] + dir * (Bc*HHc);
    float* h_out = g_ench[(t + 1) & 1] + dir * (Bc*HHc);

    __shared__ float sh[HHc * 36];
    for (int j = threadIdx.x; j < Bc*HHc; j += 256) {
        int k = j >> 5, b = j & 31;
        sh[k*36 + b] = h_in[b*HHc + k];
    }
    __syncthreads();

    const int col = threadIdx.x >> 3;
    const int b0  = (threadIdx.x & 7) * 4;
    const int gg = col >> 3, uu = col & 7;
    const int gcol = gg*HHc + u0 + uu;
    const float* wrow = whh + (size_t)gcol * HHc;
    float a0 = 0.f, a1 = 0.f, a2 = 0.f, a3 = 0.f;
#pragma unroll 4
    for (int k = 0; k < HHc; k += 4) {
        float4 w4 = *(const float4*)(wrow + k);
        float4 h0 = *(const float4*)&sh[(k+0)*36 + b0];
        float4 h1 = *(const float4*)&sh[(k+1)*36 + b0];
        float4 h2 = *(const float4*)&sh[(k+2)*36 + b0];
        float4 h3 = *(const float4*)&sh[(k+3)*36 + b0];
        a0 += w4.x*h0.x + w4.y*h1.x + w4.z*h2.x + w4.w*h3.x;
        a1 += w4.x*h0.y + w4.y*h1.y + w4.z*h2.y + w4.w*h3.y;
        a2 += w4.x*h0.z + w4.y*h1.z + w4.z*h2.z + w4.w*h3.z;
        a3 += w4.x*h0.w + w4.y*h1.w + w4.z*h2.w + w4.w*h3.w;
    }
    __syncthreads();
    sh[col*33 + b0 + 0] = a0;
    sh[col*33 + b0 + 1] = a1;
    sh[col*33 + b0 + 2] = a2;
    sh[col*33 + b0 + 3] = a3;
    __syncthreads();

    const int b  = threadIdx.x & 31;
    const int u2 = threadIdx.x >> 5;
    const int u  = u0 + u2;
    const float* prebt = pre + (size_t)(b*Tc + t) * (4*HHc);
    float gi = sh[(0*8 + u2)*33 + b] + prebt[0*HHc + u];
    float gf = sh[(1*8 + u2)*33 + b] + prebt[1*HHc + u];
    float gc = sh[(2*8 + u2)*33 + b] + prebt[2*HHc + u];
    float go = sh[(3*8 + u2)*33 + b] + prebt[3*HHc + u];
    float cold = cst[b*HHc + u];
    float cnew = sigm(gf) * cold + sigm(gi) * tanhf(gc);
    float hnew = sigm(go) * tanhf(cnew);
    cst[b*HHc + u] = cnew;
    h_out[b*HHc + u] = hnew;
    g_hiddens[(size_t)(b*Tc + t)*Hc + dir*HHc + u] = hnew;
    g_hsum[b*Hc + dir*HHc + u] += hnew;
    g_csum[b*Hc + dir*HHc + u] += cnew;
}

// ---------------- mean ----------------
__global__ void k_mean() {
    int i = blockIdx.x * blockDim.x + threadIdx.x;
    if (i < Bc*Hc) {
        g_dech[0][i] = g_hsum[i] * (1.0f / Tc);
        g_decc[i]    = g_csum[i] * (1.0f / Tc);
    }
}

// ---------------- decoder LSTM step ----------------
__global__ __launch_bounds__(256, 1)
void k_dec_step(int ty, const float* __restrict__ whh) {
    const int u0 = blockIdx.x * 8;
    const float* h_in = g_dech[ty & 1];
    float* h_out = g_dech[(ty + 1) & 1];
    __shared__ float sh[256 * 36];

    const int col = threadIdx.x >> 3;
    const int b0  = (threadIdx.x & 7) * 4;
    const int gg = col >> 3, uu = col & 7;
    const int gcol = gg*Hc + u0 + uu;
    const float* wrow = whh + (size_t)gcol * Hc;
    float a0 = 0.f, a1 = 0.f, a2 = 0.f, a3 = 0.f;

    for (int kc = 0; kc < Hc; kc += 256) {
        for (int j = threadIdx.x; j < Bc*256; j += 256) {
            int k = j >> 5, bb = j & 31;
            sh[k*36 + bb] = h_in[bb*Hc + kc + k];
        }
        __syncthreads();
#pragma unroll 4
        for (int k = 0; k < 256; k += 4) {
            float4 w4 = *(const float4*)(wrow + kc + k);
            float4 h0 = *(const float4*)&sh[(k+0)*36 + b0];
            float4 h1 = *(const float4*)&sh[(k+1)*36 + b0];
            float4 h2 = *(const float4*)&sh[(k+2)*36 + b0];
            float4 h3 = *(const float4*)&sh[(k+3)*36 + b0];
            a0 += w4.x*h0.x + w4.y*h1.x + w4.z*h2.x + w4.w*h3.x;
            a1 += w4.x*h0.y + w4.y*h1.y + w4.z*h2.y + w4.w*h3.y;
            a2 += w4.x*h0.z + w4.y*h1.z + w4.z*h2.z + w4.w*h3.z;
            a3 += w4.x*h0.w + w4.y*h1.w + w4.z*h2.w + w4.w*h3.w;
        }
        __syncthreads();
    }
    sh[col*33 + b0 + 0] = a0;
    sh[col*33 + b0 + 1] = a1;
    sh[col*33 + b0 + 2] = a2;
    sh[col*33 + b0 + 3] = a3;
    __syncthreads();

    const int b  = threadIdx.x & 31;
    const int u2 = threadIdx.x >> 5;
    const int u  = u0 + u2;
    const float* prebt = g_decpre + (size_t)(b*TYc + ty) * (4*Hc);
    float gi = sh[(0*8 + u2)*33 + b] + prebt[0*Hc + u];
    float gf = sh[(1*8 + u2)*33 + b] + prebt[1*Hc + u];
    float gc = sh[(2*8 + u2)*33 + b] + prebt[2*Hc + u];
    float go = sh[(3*8 + u2)*33 + b] + prebt[3*Hc + u];
    float cold = g_decc[b*Hc + u];
    float cnew = sigm(gf) * cold + sigm(gi) * tanhf(gc);
    float hnew = sigm(go) * tanhf(cnew);
    g_decc[b*Hc + u] = cnew;
    h_out[b*Hc + u] = hnew;
    g_outhid[(size_t)(b*TYc + ty)*(2*Hc) + u] = hnew;
}

// ---------------- attention ----------------
__global__ __launch_bounds__(256, 1)
void k_dec_attn(int ty) {
    const int b = blockIdx.x;
    const float* h = g_dech[(ty + 1) & 1] + b*Hc;
    __shared__ float hs[Hc];
    __shared__ float sc[Tc];
    __shared__ float red[8];
    for (int i = threadIdx.x; i < Hc; i += 256) hs[i] = h[i];
    __syncthreads();

    const int tp = threadIdx.x >> 1;
    const int half = threadIdx.x & 1;
    const float* hid = g_hiddens + (size_t)(b*Tc + tp)*Hc + half*256;
    const float* hq = hs + half*256;
    float s = 0.f;
#pragma unroll 4
    for (int k = 0; k < 256; k += 4) {
        float4 a = *(const float4*)(hid + k);
        float4 c = *(const float4*)(hq + k);
        s += a.x*c.x + a.y*c.y + a.z*c.z + a.w*c.w;
    }
    s += __shfl_down_sync(0xffffffffu, s, 1);
    if (half == 0) sc[tp] = s;
    __syncthreads();

    const int lane = threadIdx.x & 31, wid = threadIdx.x >> 5;
    float v = (threadIdx.x < Tc) ? sc[threadIdx.x] : -1e30f;
    float m = v;
    for (int o = 16; o; o >>= 1) m = fmaxf(m, __shfl_xor_sync(0xffffffffu, m, o));
    if (!lane) red[wid] = m;
    __syncthreads();
    if (!wid) {
        float xx = (lane < 8) ? red[lane] : -1e30f;
        for (int o = 4; o; o >>= 1) xx = fmaxf(xx, __shfl_xor_sync(0xffffffffu, xx, o));
        if (!lane) red[0] = xx;
    }
    __syncthreads();
    m = red[0];
    float e = (threadIdx.x < Tc) ? expf(v - m) : 0.f;
    float ssum = e;
    for (int o = 16; o; o >>= 1) ssum += __shfl_xor_sync(0xffffffffu, ssum, o);
    __syncthreads();
    if (!lane) red[wid] = ssum;
    __syncthreads();
    if (!wid) {
        float xx = (lane < 8) ? red[lane] : 0.f;
        for (int o = 4; o; o >>= 1) xx += __shfl_xor_sync(0xffffffffu, xx, o);
        if (!lane) red[0] = xx;
    }
    __syncthreads();
    float inv = 1.f / red[0];
    if (threadIdx.x < Tc) sc[threadIdx.x] = e * inv;
    __syncthreads();

    float* octx = g_outhid + (size_t)(b*TYc + ty)*(2*Hc) + Hc;
    for (int d = threadIdx.x; d < Hc; d += 256) {
        float a = 0.f;
#pragma unroll 8
        for (int tq = 0; tq < Tc; tq++) a += sc[tq] * g_hiddens[(size_t)(b*Tc + tq)*Hc + d];
        octx[d] = a;
    }
}

// ---------------- in-place log_softmax ----------------
__global__ __launch_bounds__(256)
void k_logsoftmax(float* __restrict__ out) {
    const int row = blockIdx.x;
    float* p = out + (size_t)row * Vc;
    __shared__ float red[8];
    const int lane = threadIdx.x & 31, wid = threadIdx.x >> 5;
    float m = -1e30f;
    for (int i = threadIdx.x; i < Vc; i += 256) m = fmaxf(m, p[i]);
    for (int o = 16; o; o >>= 1) m = fmaxf(m, __shfl_xor_sync(0xffffffffu, m, o));
    if (!lane) red[wid] = m;
    __syncthreads();
    if (!wid) {
        float xx = (lane < 8) ? red[lane] : -1e30f;
        for (int o = 4; o; o >>= 1) xx = fmaxf(xx, __shfl_xor_sync(0xffffffffu, xx, o));
        if (!lane) red[0] = xx;
    }
    __syncthreads();
    m = red[0];
    float s = 0.f;
    for (int i = threadIdx.x; i < Vc; i += 256) s += expf(p[i] - m);
    for (int o = 16; o; o >>= 1) s += __shfl_xor_sync(0xffffffffu, s, o);
    __syncthreads();
    if (!lane) red[wid] = s;
    __syncthreads();
    if (!wid) {
        float xx = (lane < 8) ? red[lane] : 0.f;
        for (int o = 4; o; o >>= 1) xx += __shfl_xor_sync(0xffffffffu, xx, o);
        if (!lane) red[0] = xx;
    }
    __syncthreads();
    float lse = m + logf(red[0]);
    for (int i = threadIdx.x; i < Vc; i += 256) p[i] -= lse;
}

__global__ void k_copy_tail(float* __restrict__ dst) {
    int i = blockIdx.x * blockDim.x + threadIdx.x;
    if (i < Bc*TYc*2*Hc) dst[i] = g_outhid[i];
}

// ---------------- launch ----------------
extern "C" void kernel_launch(void* const* d_in, const int* in_sizes, int n_in,
                              void* d_out, int out_size) {
    (void)in_sizes; (void)n_in;
    const int*   x      = (const int*)  d_in[0];
    const float* xmask  = (const float*)d_in[1];
    const int*   y      = (const int*)  d_in[2];
    const float* embed  = (const float*)d_in[3];
    const float* w_ih_f = (const float*)d_in[4];
    const float* w_hh_f = (const float*)d_in[5];
    const float* b_ih_f = (const float*)d_in[6];
    const float* b_hh_f = (const float*)d_in[7];
    const float* w_ih_b = (const float*)d_in[8];
    const float* w_hh_b = (const float*)d_in[9];
    const float* b_ih_b = (const float*)d_in[10];
    const float* b_hh_b = (const float*)d_in[11];
    const float* w_ih_d = (const float*)d_in[12];
    const float* w_hh_d = (const float*)d_in[13];
    const float* b_ih_d = (const float*)d_in[14];
    const float* b_hh_d = (const float*)d_in[15];
    const float* W_out  = (const float*)d_in[16];
    const float* b_out  = (const float*)d_in[17];
    float* out = (float*)d_out;

    void *p_xemb, *p_xbemb, *p_yemb, *p_pref, *p_preb, *p_decpre, *p_outhid, *p_xback;
    cudaGetSymbolAddress(&p_xemb,   g_xemb);
    cudaGetSymbolAddress(&p_xbemb,  g_xbemb);
    cudaGetSymbolAddress(&p_yemb,   g_yemb);
    cudaGetSymbolAddress(&p_pref,   g_encpre_f);
    cudaGetSymbolAddress(&p_preb,   g_encpre_b);
    cudaGetSymbolAddress(&p_decpre, g_decpre);
    cudaGetSymbolAddress(&p_outhid, g_outhid);
    cudaGetSymbolAddress(&p_xback,  g_xback);

    k_init<<<128, 256>>>();
    k_xback<<<1, 32>>>(x, xmask);
    k_gather<<<Bc*Tc, 128>>>(x, embed, (float*)p_xemb);
    k_gather<<<Bc*Tc, 128>>>((const int*)p_xback, embed, (float*)p_xbemb);
    k_gather<<<Bc*TYc, 128>>>(y, embed, (float*)p_yemb);

    // time-batched input-side GEMMs (tensor mma.sync tf32), fold both biases
    k_mma<<<dim3((Bc*Tc)/128, (4*HHc)/128), 256>>>(
        (const float*)p_xemb,  w_ih_f, b_ih_f, b_hh_f, (float*)p_pref,   Bc*Tc,  4*HHc, Ec);
    k_mma<<<dim3((Bc*Tc)/128, (4*HHc)/128), 256>>>(
        (const float*)p_xbemb, w_ih_b, b_ih_b, b_hh_b, (float*)p_preb,   Bc*Tc,  4*HHc, Ec);
    k_mma<<<dim3((Bc*TYc)/128, (4*Hc)/128), 256>>>(
        (const float*)p_yemb,  w_ih_d, b_ih_d, b_hh_d, (float*)p_decpre, Bc*TYc, 4*Hc,  Ec);

    for (int t = 0; t < Tc; t++)
        k_enc_step<<<dim3(HHc/8, 2), 256>>>(t, w_hh_f, w_hh_b);

    k_mean<<<(Bc*Hc + 255)/256, 256>>>();

    for (int ty = 0; ty < TYc; ty++) {
        k_dec_step<<<Hc/8, 256>>>(ty, w_hh_d);
        k_dec_attn<<<Bc, 256>>>(ty);
    }

    // projection: logits straight into d_out (mma.sync tf32), then in-place log_softmax
    // M-blocks on blockIdx.x so a wave covers all M for each N-block (W_out reuse in L2)
    k_mma<<<dim3((Bc*TYc)/128, Vc/128), 256>>>(
        (const float*)p_outhid, W_out, b_out, nullptr, out, Bc*TYc, Vc, 2*Hc);
    k_logsoftmax<<<Bc*TYc, 256>>>(out);

    long long need = (long long)Bc*TYc*Vc + (long long)Bc*TYc*2*Hc;
    if ((long long)out_size >= need)
        k_copy_tail<<<(Bc*TYc*2*Hc + 255)/256, 256>>>(out + (size_t)Bc*TYc*Vc);
}

// round 8
// speedup vs baseline: 3.0692x; 3.0692x over previous
#include <cuda_runtime.h>
#include <math.h>
#include <stdint.h>

// Problem dims
#define Bc  32
#define Tc  128
#define TYc 64
#define Ec  512
#define Hc  512
#define HHc 256
#define Vc  32000

// ---------------- scratch (__device__ globals; no allocations) ----------------
__device__ float g_xemb  [Bc*Tc*Ec];
__device__ float g_xbemb [Bc*Tc*Ec];
__device__ float g_yemb  [Bc*TYc*Ec];
__device__ int   g_xback [Bc*Tc];
__device__ float g_encpre_f[Bc*Tc*4*HHc];
__device__ float g_encpre_b[Bc*Tc*4*HHc];
__device__ float g_decpre  [Bc*TYc*4*Hc];
__device__ float g_ench[2][2*Bc*HHc];   // ping-pong h, [pp][dir*8192 + u*32 + b]
__device__ float g_hiddens[Bc*Tc*Hc];   // [b][t][fwd|bwd]
__device__ float g_dech[2][Bc*Hc];      // ping-pong decoder h, [pp][u*32 + b]
__device__ float g_decc0[Bc*Hc];        // decoder c init, [u*32 + b]
__device__ float g_outhid[Bc*TYc*2*Hc]; // [b][ty][h|ctx]

// software grid barrier state (reset by k_init every replay)
__device__ unsigned g_cnt[4];
__device__ volatile unsigned g_flag[4];

__device__ __forceinline__ float sigm(float x) { return 1.f / (1.f + expf(-x)); }

__device__ __forceinline__ void gbar(int idx, unsigned phase, unsigned nb) {
    __syncthreads();
    if (threadIdx.x == 0) {
        __threadfence();
        unsigned old = atomicAdd(&g_cnt[idx], 1u);
        if (old == phase * nb - 1u) g_flag[idx] = phase;
        else while (g_flag[idx] < phase) { }
    }
    __syncthreads();
}

// ======================================================================
// mma.sync tf32 GEMM: C[M,N] = A[M,K] @ W[N,K]^T (+b1[n] +b2[n])
// (unchanged from R5 — passing, rel_err 2.3e-4)
// ======================================================================
#define KC 16
#define PITCH 20

__device__ __forceinline__ void mma_tf32(float* d, const uint32_t* a, const uint32_t* b) {
    asm volatile(
        "mma.sync.aligned.m16n8k8.row.col.f32.tf32.tf32.f32 "
        "{%0,%1,%2,%3}, {%4,%5,%6,%7}, {%8,%9}, {%0,%1,%2,%3};\n"
        : "+f"(d[0]), "+f"(d[1]), "+f"(d[2]), "+f"(d[3])
        : "r"(a[0]), "r"(a[1]), "r"(a[2]), "r"(a[3]), "r"(b[0]), "r"(b[1]));
}

__global__ __launch_bounds__(256, 2)
void k_mma(const float* __restrict__ A, const float* __restrict__ W,
           const float* __restrict__ b1, const float* __restrict__ b2,
           float* __restrict__ C, int M, int N, int K) {
    __shared__ float sA[2][128 * PITCH];
    __shared__ float sB[2][128 * PITCH];

    const int tid  = threadIdx.x;
    const int wid  = tid >> 5;
    const int lane = tid & 31;
    const int g    = lane >> 2;
    const int t    = lane & 3;
    const int wm   = (wid & 1) * 64;
    const int wn   = (wid >> 1) * 32;
    const int bm   = blockIdx.x * 128;
    const int bn   = blockIdx.y * 128;

    const float* Ab = A + (size_t)bm * K;
    const float* Wb = W + (size_t)bn * K;

    const int ldrow = tid >> 2;
    const int ldch  = (tid & 3) * 4;

#define LOAD_STAGE(KC0, S) do { \
    _Pragma("unroll") \
    for (int _i = 0; _i < 2; _i++) { \
        int _r = ldrow + _i * 64; \
        uint32_t _da; \
        asm("{ .reg .u64 t; cvta.to.shared.u64 t, %1; cvt.u32.u64 %0, t; }" \
            : "=r"(_da) : "l"(&sA[S][_r * PITCH + ldch])); \
        const float* _sa = Ab + (size_t)_r * K + (KC0) + ldch; \
        asm volatile("cp.async.cg.shared.global [%0], [%1], 16;" :: "r"(_da), "l"(_sa)); \
        uint32_t _db; \
        asm("{ .reg .u64 t; cvta.to.shared.u64 t, %1; cvt.u32.u64 %0, t; }" \
            : "=r"(_db) : "l"(&sB[S][_r * PITCH + ldch])); \
        const float* _sb = Wb + (size_t)_r * K + (KC0) + ldch; \
        asm volatile("cp.async.cg.shared.global [%0], [%1], 16;" :: "r"(_db), "l"(_sb)); \
    } \
    asm volatile("cp.async.commit_group;" ::: "memory"); \
} while (0)

    float acc[4][4][4];
#pragma unroll
    for (int i = 0; i < 4; i++)
#pragma unroll
        for (int j = 0; j < 4; j++)
#pragma unroll
            for (int r = 0; r < 4; r++) acc[i][j][r] = 0.f;

    const int NS = K / KC;
    LOAD_STAGE(0, 0);
    LOAD_STAGE(KC, 1);

    for (int s = 0; s < NS; s++) {
        if (s + 1 < NS) asm volatile("cp.async.wait_group 1;" ::: "memory");
        else            asm volatile("cp.async.wait_group 0;" ::: "memory");
        __syncthreads();
        const int buf = s & 1;
        const float* pa = &sA[buf][0];
        const float* pb = &sB[buf][0];
#pragma unroll
        for (int ks = 0; ks < 2; ks++) {
            const int kb = ks * 8 + t;
            uint32_t af[4][4], bf[4][2];
#pragma unroll
            for (int mt = 0; mt < 4; mt++) {
                const float* sa = pa + (wm + mt * 16 + g) * PITCH + kb;
                af[mt][0] = __float_as_uint(sa[0]);
                af[mt][1] = __float_as_uint(sa[8 * PITCH]);
                af[mt][2] = __float_as_uint(sa[4]);
                af[mt][3] = __float_as_uint(sa[8 * PITCH + 4]);
            }
#pragma unroll
            for (int nt = 0; nt < 4; nt++) {
                const float* sb = pb + (wn + nt * 8 + g) * PITCH + kb;
                bf[nt][0] = __float_as_uint(sb[0]);
                bf[nt][1] = __float_as_uint(sb[4]);
            }
#pragma unroll
            for (int mt = 0; mt < 4; mt++)
#pragma unroll
                for (int nt = 0; nt < 4; nt++)
                    mma_tf32(acc[mt][nt], af[mt], bf[nt]);
        }
        __syncthreads();
        if (s + 2 < NS) LOAD_STAGE((s + 2) * KC, buf);
    }

#pragma unroll
    for (int nt = 0; nt < 4; nt++) {
        const int n0 = bn + wn + nt * 8 + 2 * t;
        float bb0 = 0.f, bb1 = 0.f;
        if (b1) { bb0 += b1[n0]; bb1 += b1[n0 + 1]; }
        if (b2) { bb0 += b2[n0]; bb1 += b2[n0 + 1]; }
#pragma unroll
        for (int mt = 0; mt < 4; mt++) {
            const int m0 = bm + wm + mt * 16 + g;
            float2 v0 = make_float2(acc[mt][nt][0] + bb0, acc[mt][nt][1] + bb1);
            float2 v1 = make_float2(acc[mt][nt][2] + bb0, acc[mt][nt][3] + bb1);
            *(float2*)(C + (size_t)m0 * N + n0)       = v0;
            *(float2*)(C + (size_t)(m0 + 8) * N + n0) = v1;
        }
    }
#undef LOAD_STAGE
}

// ---------------- init (zero h0, reset barriers) ----------------
__global__ void k_init() {
    int i = blockIdx.x * blockDim.x + threadIdx.x;
    if (i < 2*2*Bc*HHc) (&g_ench[0][0])[i] = 0.f;
    if (i < Bc*Tc)      g_xback[i] = 0;
    if (i < 4)          { g_cnt[i] = 0u; g_flag[i] = 0u; }
}

// ---------------- pad-aware reversed tokens ----------------
__global__ void k_xback(const int* __restrict__ x, const float* __restrict__ mask) {
    int b = threadIdx.x;
    if (b >= Bc) return;
    float s = 0.f;
    for (int t = 0; t < Tc; t++) s += mask[b*Tc + t];
    int pad = Tc - (int)(s + 0.5f);
    for (int j = 0; j < Tc; j++) {
        int r = Tc - 1 - j - pad;
        if (r < 0) r = 0;
        g_xback[b*Tc + r] = x[b*Tc + j];
    }
}

// ---------------- embedding gather ----------------
__global__ void k_gather(const int* __restrict__ idx, const float* __restrict__ embed,
                         float* __restrict__ out) {
    int row = blockIdx.x;
    int e = threadIdx.x;
    const float4* src = (const float4*)embed + (size_t)idx[row] * (Ec/4);
    ((float4*)out)[(size_t)row * (Ec/4) + e] = src[e];
}

// ======================================================================
// Persistent encoder scan: 64 blocks (32 per direction), weights in smem,
// h ping-pong in global [u][b], c/hsum/csum in registers, per-dir barrier.
// ======================================================================
__global__ __launch_bounds__(256, 1)
void k_enc_scan(const float* __restrict__ whh_f, const float* __restrict__ whh_b) {
    extern __shared__ float sm[];
    float* wt = sm;                 // [256][32] transposed weights
    float* sh = sm + 256*32;        // [256][33] h staged [k][b]
    float* gb = sh + 256*33;        // [32][33] gates [col][b]

    const int tid  = threadIdx.x;
    const int dir  = blockIdx.x >> 5;
    const int ub   = blockIdx.x & 31;
    const int u0   = ub * 8;
    const float* whh = dir ? whh_b : whh_f;
    const float* pre = dir ? g_encpre_b : g_encpre_f;

    // one-time: load weight slice transposed wt[k][col], col = gate*8 + uu
    for (int j = tid; j < 32*256; j += 256) {
        int col = j & 31, k = j >> 5;
        int gg = col >> 3, uu = col & 7;
        wt[k*32 + col] = whh[(size_t)(gg*HHc + u0 + uu)*HHc + k];
    }

    const int lane = tid & 31;
    const int wy   = tid >> 5;
    const int c0   = wy * 4;        // compute: 4 cols, batch = lane
    const int cb   = tid & 31;      // cell: batch
    const int cu   = tid >> 5;      // cell: unit offset 0..7
    const int ug   = dir*HHc + u0 + cu;
    float creg = 0.f, hsum = 0.f, csum = 0.f;
    __syncthreads();

    for (int t = 0; t < Tc; t++) {
        const float* h_in = &g_ench[t & 1][dir * (Bc*HHc)];
        // stage h [k][b] -> smem (L2-coherent reads: ping-pong addresses reused)
#pragma unroll
        for (int i = 0; i < 8; i++) {
            int idx = tid + i * 256;               // float4 index < 2048
            float4 v = __ldcg((const float4*)h_in + idx);
            int j = idx * 4;
            int k = j >> 5, b = j & 31;
            sh[k*33 + b + 0] = v.x; sh[k*33 + b + 1] = v.y;
            sh[k*33 + b + 2] = v.z; sh[k*33 + b + 3] = v.w;
        }
        // prefetch pre-activations for the cell update (latency hidden by compute)
        const float* pbt = pre + (size_t)(cb*Tc + t) * (4*HHc) + u0 + cu;
        float pf0 = pbt[0*HHc], pf1 = pbt[1*HHc], pf2 = pbt[2*HHc], pf3 = pbt[3*HHc];
        __syncthreads();

        float a0 = 0.f, a1 = 0.f, a2 = 0.f, a3 = 0.f;
#pragma unroll 8
        for (int k = 0; k < 256; k++) {
            float4 wv = *(const float4*)&wt[k*32 + c0];
            float hv = sh[k*33 + lane];
            a0 += wv.x * hv; a1 += wv.y * hv; a2 += wv.z * hv; a3 += wv.w * hv;
        }
        gb[(c0+0)*33 + lane] = a0;
        gb[(c0+1)*33 + lane] = a1;
        gb[(c0+2)*33 + lane] = a2;
        gb[(c0+3)*33 + lane] = a3;
        __syncthreads();

        float gi = gb[(0*8 + cu)*33 + cb] + pf0;
        float gf = gb[(1*8 + cu)*33 + cb] + pf1;
        float gc = gb[(2*8 + cu)*33 + cb] + pf2;
        float go = gb[(3*8 + cu)*33 + cb] + pf3;
        creg = sigm(gf) * creg + sigm(gi) * tanhf(gc);
        float hnew = sigm(go) * tanhf(creg);
        hsum += hnew; csum += creg;
        g_ench[(t+1) & 1][dir*(Bc*HHc) + (u0+cu)*32 + cb] = hnew;
        g_hiddens[(size_t)(cb*Tc + t)*Hc + ug] = hnew;

        gbar(dir, (unsigned)(t + 1), 32u);   // per-direction grid barrier
    }

    // decoder init state (mean over T) straight from register sums
    g_dech[0][ug*32 + cb] = hsum * (1.0f / Tc);
    g_decc0[ug*32 + cb]   = csum * (1.0f / Tc);
}

// ======================================================================
// Persistent decoder scan: 64 blocks, 64KB weight slice + h stage in smem.
// LSTM only — attention is batch-parallel afterwards.
// ======================================================================
__global__ __launch_bounds__(256, 1)
void k_dec_scan(const float* __restrict__ whh) {
    extern __shared__ float sm[];
    float* wt = sm;                 // [512][32]
    float* sh = sm + 512*32;        // [512][33]
    float* gb = sh + 512*33;        // [32][33]

    const int tid  = threadIdx.x;
    const int u0   = blockIdx.x * 8;

    for (int j = tid; j < 32*512; j += 256) {
        int col = j & 31, k = j >> 5;
        int gg = col >> 3, uu = col & 7;
        wt[k*32 + col] = whh[(size_t)(gg*Hc + u0 + uu)*Hc + k];
    }

    const int lane = tid & 31;
    const int wy   = tid >> 5;
    const int c0   = wy * 4;
    const int cb   = tid & 31;
    const int cu   = tid >> 5;
    float creg;
    __syncthreads();
    creg = g_decc0[(u0+cu)*32 + cb];

    for (int ty = 0; ty < TYc; ty++) {
        const float* h_in = &g_dech[ty & 1][0];
#pragma unroll
        for (int i = 0; i < 16; i++) {
            int idx = tid + i * 256;               // float4 index < 4096
            float4 v = __ldcg((const float4*)h_in + idx);
            int j = idx * 4;
            int k = j >> 5, b = j & 31;
            sh[k*33 + b + 0] = v.x; sh[k*33 + b + 1] = v.y;
            sh[k*33 + b + 2] = v.z; sh[k*33 + b + 3] = v.w;
        }
        const float* pbt = g_decpre + (size_t)(cb*TYc + ty) * (4*Hc) + u0 + cu;
        float pf0 = pbt[0*Hc], pf1 = pbt[1*Hc], pf2 = pbt[2*Hc], pf3 = pbt[3*Hc];
        __syncthreads();

        float a0 = 0.f, a1 = 0.f, a2 = 0.f, a3 = 0.f;
#pragma unroll 8
        for (int k = 0; k < 512; k++) {
            float4 wv = *(const float4*)&wt[k*32 + c0];
            float hv = sh[k*33 + lane];
            a0 += wv.x * hv; a1 += wv.y * hv; a2 += wv.z * hv; a3 += wv.w * hv;
        }
        gb[(c0+0)*33 + lane] = a0;
        gb[(c0+1)*33 + lane] = a1;
        gb[(c0+2)*33 + lane] = a2;
        gb[(c0+3)*33 + lane] = a3;
        __syncthreads();

        float gi = gb[(0*8 + cu)*33 + cb] + pf0;
        float gf = gb[(1*8 + cu)*33 + cb] + pf1;
        float gc = gb[(2*8 + cu)*33 + cb] + pf2;
        float go = gb[(3*8 + cu)*33 + cb] + pf3;
        creg = sigm(gf) * creg + sigm(gi) * tanhf(gc);
        float hnew = sigm(go) * tanhf(creg);
        g_dech[(ty+1) & 1][(u0+cu)*32 + cb] = hnew;
        g_outhid[(size_t)(cb*TYc + ty)*(2*Hc) + u0 + cu] = hnew;

        gbar(2, (unsigned)(ty + 1), 64u);
    }
}

// ---------------- attention, batch-parallel over (b, ty) ----------------
__global__ __launch_bounds__(256, 1)
void k_attn() {
    const int b  = blockIdx.x;
    const int ty = blockIdx.y;
    const float* h = g_outhid + (size_t)(b*TYc + ty)*(2*Hc);   // decoder h for this step
    __shared__ float hs[Hc];
    __shared__ float sc[Tc];
    __shared__ float red[8];
    for (int i = threadIdx.x; i < Hc; i += 256) hs[i] = h[i];
    __syncthreads();

    const int tp = threadIdx.x >> 1;
    const int half = threadIdx.x & 1;
    const float* hid = g_hiddens + (size_t)(b*Tc + tp)*Hc + half*256;
    const float* hq = hs + half*256;
    float s = 0.f;
#pragma unroll 4
    for (int k = 0; k < 256; k += 4) {
        float4 a = *(const float4*)(hid + k);
        float4 c = *(const float4*)(hq + k);
        s += a.x*c.x + a.y*c.y + a.z*c.z + a.w*c.w;
    }
    s += __shfl_down_sync(0xffffffffu, s, 1);
    if (half == 0) sc[tp] = s;
    __syncthreads();

    const int lane = threadIdx.x & 31, wid = threadIdx.x >> 5;
    float v = (threadIdx.x < Tc) ? sc[threadIdx.x] : -1e30f;
    float m = v;
    for (int o = 16; o; o >>= 1) m = fmaxf(m, __shfl_xor_sync(0xffffffffu, m, o));
    if (!lane) red[wid] = m;
    __syncthreads();
    if (!wid) {
        float xx = (lane < 8) ? red[lane] : -1e30f;
        for (int o = 4; o; o >>= 1) xx = fmaxf(xx, __shfl_xor_sync(0xffffffffu, xx, o));
        if (!lane) red[0] = xx;
    }
    __syncthreads();
    m = red[0];
    float e = (threadIdx.x < Tc) ? expf(v - m) : 0.f;
    float ssum = e;
    for (int o = 16; o; o >>= 1) ssum += __shfl_xor_sync(0xffffffffu, ssum, o);
    __syncthreads();
    if (!lane) red[wid] = ssum;
    __syncthreads();
    if (!wid) {
        float xx = (lane < 8) ? red[lane] : 0.f;
        for (int o = 4; o; o >>= 1) xx += __shfl_xor_sync(0xffffffffu, xx, o);
        if (!lane) red[0] = xx;
    }
    __syncthreads();
    float inv = 1.f / red[0];
    if (threadIdx.x < Tc) sc[threadIdx.x] = e * inv;
    __syncthreads();

    float* octx = g_outhid + (size_t)(b*TYc + ty)*(2*Hc) + Hc;
    for (int d = threadIdx.x; d < Hc; d += 256) {
        float a = 0.f;
#pragma unroll 8
        for (int tq = 0; tq < Tc; tq++) a += sc[tq] * g_hiddens[(size_t)(b*Tc + tq)*Hc + d];
        octx[d] = a;
    }
}

// ---------------- in-place log_softmax ----------------
__global__ __launch_bounds__(256)
void k_logsoftmax(float* __restrict__ out) {
    const int row = blockIdx.x;
    float* p = out + (size_t)row * Vc;
    __shared__ float red[8];
    const int lane = threadIdx.x & 31, wid = threadIdx.x >> 5;
    float m = -1e30f;
    for (int i = threadIdx.x; i < Vc; i += 256) m = fmaxf(m, p[i]);
    for (int o = 16; o; o >>= 1) m = fmaxf(m, __shfl_xor_sync(0xffffffffu, m, o));
    if (!lane) red[wid] = m;
    __syncthreads();
    if (!wid) {
        float xx = (lane < 8) ? red[lane] : -1e30f;
        for (int o = 4; o; o >>= 1) xx = fmaxf(xx, __shfl_xor_sync(0xffffffffu, xx, o));
        if (!lane) red[0] = xx;
    }
    __syncthreads();
    m = red[0];
    float s = 0.f;
    for (int i = threadIdx.x; i < Vc; i += 256) s += expf(p[i] - m);
    for (int o = 16; o; o >>= 1) s += __shfl_xor_sync(0xffffffffu, s, o);
    __syncthreads();
    if (!lane) red[wid] = s;
    __syncthreads();
    if (!wid) {
        float xx = (lane < 8) ? red[lane] : 0.f;
        for (int o = 4; o; o >>= 1) xx += __shfl_xor_sync(0xffffffffu, xx, o);
        if (!lane) red[0] = xx;
    }
    __syncthreads();
    float lse = m + logf(red[0]);
    for (int i = threadIdx.x; i < Vc; i += 256) p[i] -= lse;
}

__global__ void k_copy_tail(float* __restrict__ dst) {
    int i = blockIdx.x * blockDim.x + threadIdx.x;
    if (i < Bc*TYc*2*Hc) dst[i] = g_outhid[i];
}

// ---------------- launch ----------------
extern "C" void kernel_launch(void* const* d_in, const int* in_sizes, int n_in,
                              void* d_out, int out_size) {
    (void)in_sizes; (void)n_in;
    const int*   x      = (const int*)  d_in[0];
    const float* xmask  = (const float*)d_in[1];
    const int*   y      = (const int*)  d_in[2];
    const float* embed  = (const float*)d_in[3];
    const float* w_ih_f = (const float*)d_in[4];
    const float* w_hh_f = (const float*)d_in[5];
    const float* b_ih_f = (const float*)d_in[6];
    const float* b_hh_f = (const float*)d_in[7];
    const float* w_ih_b = (const float*)d_in[8];
    const float* w_hh_b = (const float*)d_in[9];
    const float* b_ih_b = (const float*)d_in[10];
    const float* b_hh_b = (const float*)d_in[11];
    const float* w_ih_d = (const float*)d_in[12];
    const float* w_hh_d = (const float*)d_in[13];
    const float* b_ih_d = (const float*)d_in[14];
    const float* b_hh_d = (const float*)d_in[15];
    const float* W_out  = (const float*)d_in[16];
    const float* b_out  = (const float*)d_in[17];
    float* out = (float*)d_out;

    void *p_xemb, *p_xbemb, *p_yemb, *p_pref, *p_preb, *p_decpre, *p_outhid, *p_xback;
    cudaGetSymbolAddress(&p_xemb,   g_xemb);
    cudaGetSymbolAddress(&p_xbemb,  g_xbemb);
    cudaGetSymbolAddress(&p_yemb,   g_yemb);
    cudaGetSymbolAddress(&p_pref,   g_encpre_f);
    cudaGetSymbolAddress(&p_preb,   g_encpre_b);
    cudaGetSymbolAddress(&p_decpre, g_decpre);
    cudaGetSymbolAddress(&p_outhid, g_outhid);
    cudaGetSymbolAddress(&p_xback,  g_xback);

    const int ENC_SMEM = (256*32 + 256*33 + 32*33) * 4;   //  70784 B
    const int DEC_SMEM = (512*32 + 512*33 + 32*33) * 4;   // 137344 B
    static bool attr_done = false;
    if (!attr_done) {
        cudaFuncSetAttribute(k_enc_scan, cudaFuncAttributeMaxDynamicSharedMemorySize, ENC_SMEM);
        cudaFuncSetAttribute(k_dec_scan, cudaFuncAttributeMaxDynamicSharedMemorySize, DEC_SMEM);
        attr_done = true;
    }

    k_init<<<128, 256>>>();
    k_xback<<<1, 32>>>(x, xmask);
    k_gather<<<Bc*Tc, 128>>>(x, embed, (float*)p_xemb);
    k_gather<<<Bc*Tc, 128>>>((const int*)p_xback, embed, (float*)p_xbemb);
    k_gather<<<Bc*TYc, 128>>>(y, embed, (float*)p_yemb);

    // time-batched input-side GEMMs (fold both biases)
    k_mma<<<dim3((Bc*Tc)/128, (4*HHc)/128), 256>>>(
        (const float*)p_xemb,  w_ih_f, b_ih_f, b_hh_f, (float*)p_pref,   Bc*Tc,  4*HHc, Ec);
    k_mma<<<dim3((Bc*Tc)/128, (4*HHc)/128), 256>>>(
        (const float*)p_xbemb, w_ih_b, b_ih_b, b_hh_b, (float*)p_preb,   Bc*Tc,  4*HHc, Ec);
    k_mma<<<dim3((Bc*TYc)/128, (4*Hc)/128), 256>>>(
        (const float*)p_yemb,  w_ih_d, b_ih_d, b_hh_d, (float*)p_decpre, Bc*TYc, 4*Hc,  Ec);

    // persistent scans (software grid barriers; 64 blocks <= SM count)
    k_enc_scan<<<64, 256, ENC_SMEM>>>(w_hh_f, w_hh_b);
    k_dec_scan<<<64, 256, DEC_SMEM>>>(w_hh_d);

    // attention, fully parallel over (b, ty)
    k_attn<<<dim3(Bc, TYc), 256>>>();

    // projection + log_softmax
    k_mma<<<dim3((Bc*TYc)/128, Vc/128), 256>>>(
        (const float*)p_outhid, W_out, b_out, nullptr, out, Bc*TYc, Vc, 2*Hc);
    k_logsoftmax<<<Bc*TYc, 256>>>(out);

    long long need = (long long)Bc*TYc*Vc + (long long)Bc*TYc*2*Hc;
    if ((long long)out_size >= need)
        k_copy_tail<<<(Bc*TYc*2*Hc + 255)/256, 256>>>(out + (size_t)Bc*TYc*Vc);
}

// round 9
// speedup vs baseline: 3.6513x; 1.1897x over previous
#include <cuda_runtime.h>
#include <cuda_fp16.h>
#include <math.h>
#include <stdint.h>

// Problem dims
#define Bc  32
#define Tc  128
#define TYc 64
#define Ec  512
#define Hc  512
#define HHc 256
#define Vc  32000

// ---------------- scratch (__device__ globals; no allocations) ----------------
__device__ __half g_xembh [Bc*Tc*Ec];
__device__ __half g_xbembh[Bc*Tc*Ec];
__device__ __half g_yembh [Bc*TYc*Ec];
__device__ int    g_xback [Bc*Tc];
__device__ float  g_encpre_f[Bc*Tc*4*HHc];
__device__ float  g_encpre_b[Bc*Tc*4*HHc];
__device__ float  g_decpre  [Bc*TYc*4*Hc];
__device__ float  g_ench[2][2*Bc*HHc];   // ping-pong h, [pp][dir*8192 + u*32 + b]
__device__ float  g_hiddens[Bc*Tc*Hc];   // [b][t][fwd|bwd]
__device__ float  g_dech[2][Bc*Hc];      // ping-pong decoder h, [pp][u*32 + b]
__device__ float  g_decc0[Bc*Hc];        // decoder c init, [u*32 + b]
__device__ float  g_outhid[Bc*TYc*2*Hc]; // [b][ty][h|ctx]
__device__ __half g_outhidh[Bc*TYc*2*Hc];
// fp16 weight copies
__device__ __half g_wihf_h[4*HHc*Ec];
__device__ __half g_wihb_h[4*HHc*Ec];
__device__ __half g_wihd_h[4*Hc*Ec];
__device__ __half g_Wouth [Vc*2*Hc];

// software grid barrier state (reset by k_init every replay)
__device__ unsigned g_cnt[4];
__device__ volatile unsigned g_flag[4];

__device__ __forceinline__ float sigm(float x) { return 1.f / (1.f + expf(-x)); }

__device__ __forceinline__ void gbar(int idx, unsigned phase, unsigned nb) {
    __syncthreads();
    if (threadIdx.x == 0) {
        __threadfence();
        unsigned old = atomicAdd(&g_cnt[idx], 1u);
        if (old == phase * nb - 1u) g_flag[idx] = phase;
        else while (g_flag[idx] < phase) { }
    }
    __syncthreads();
}

// ======================================================================
// fp16 mma.sync GEMM: C[M,N] = A[M,K] @ W[N,K]^T (+b1[n] +b2[n]), fp32 accum
// CTA tile 128x128, 8 warps, warp tile 64x32 (4 m16 x 4 n8), K-stage 32 halves,
// double-buffered cp.async. Requires M%128==0, N%128==0, K%32==0, K>=64.
// Pitch 40 halves = 80B (16B-aligned for cp.async, conflict-free LDS).
// ======================================================================
#define KH 32
#define PH 40

__device__ __forceinline__ void mma_f16(float* d, const uint32_t* a, const uint32_t* b) {
    asm volatile(
        "mma.sync.aligned.m16n8k16.row.col.f32.f16.f16.f32 "
        "{%0,%1,%2,%3}, {%4,%5,%6,%7}, {%8,%9}, {%0,%1,%2,%3};\n"
        : "+f"(d[0]), "+f"(d[1]), "+f"(d[2]), "+f"(d[3])
        : "r"(a[0]), "r"(a[1]), "r"(a[2]), "r"(a[3]), "r"(b[0]), "r"(b[1]));
}

__global__ __launch_bounds__(256, 2)
void k_hmma(const __half* __restrict__ A, const __half* __restrict__ W,
            const float* __restrict__ b1, const float* __restrict__ b2,
            float* __restrict__ C, int M, int N, int K) {
    __shared__ __half sA[2][128 * PH];
    __shared__ __half sB[2][128 * PH];

    const int tid  = threadIdx.x;
    const int wid  = tid >> 5;
    const int lane = tid & 31;
    const int g    = lane >> 2;
    const int t    = lane & 3;
    const int wm   = (wid & 1) * 64;
    const int wn   = (wid >> 1) * 32;
    const int bm   = blockIdx.x * 128;
    const int bn   = blockIdx.y * 128;

    const __half* Ab = A + (size_t)bm * K;
    const __half* Wb = W + (size_t)bn * K;

#define LOAD_STAGE(KC0, S) do { \
    _Pragma("unroll") \
    for (int _i = 0; _i < 2; _i++) { \
        int _idx = tid + _i * 256; \
        int _row = _idx >> 2, _seg = _idx & 3; \
        uint32_t _da; \
        asm("{ .reg .u64 t; cvta.to.shared.u64 t, %1; cvt.u32.u64 %0, t; }" \
            : "=r"(_da) : "l"(&sA[S][_row * PH + _seg * 8])); \
        const __half* _sa = Ab + (size_t)_row * K + (KC0) + _seg * 8; \
        asm volatile("cp.async.cg.shared.global [%0], [%1], 16;" :: "r"(_da), "l"(_sa)); \
        uint32_t _db; \
        asm("{ .reg .u64 t; cvta.to.shared.u64 t, %1; cvt.u32.u64 %0, t; }" \
            : "=r"(_db) : "l"(&sB[S][_row * PH + _seg * 8])); \
        const __half* _sb = Wb + (size_t)_row * K + (KC0) + _seg * 8; \
        asm volatile("cp.async.cg.shared.global [%0], [%1], 16;" :: "r"(_db), "l"(_sb)); \
    } \
    asm volatile("cp.async.commit_group;" ::: "memory"); \
} while (0)

    float acc[4][4][4];
#pragma unroll
    for (int i = 0; i < 4; i++)
#pragma unroll
        for (int j = 0; j < 4; j++)
#pragma unroll
            for (int r = 0; r < 4; r++) acc[i][j][r] = 0.f;

    const int NS = K / KH;
    LOAD_STAGE(0, 0);
    LOAD_STAGE(KH, 1);

    for (int s = 0; s < NS; s++) {
        if (s + 1 < NS) asm volatile("cp.async.wait_group 1;" ::: "memory");
        else            asm volatile("cp.async.wait_group 0;" ::: "memory");
        __syncthreads();
        const int buf = s & 1;
        const __half* pa = &sA[buf][0];
        const __half* pb = &sB[buf][0];
#pragma unroll
        for (int ks = 0; ks < 2; ks++) {
            const int kb = ks * 16 + 2 * t;
            uint32_t af[4][4], bf[4][2];
#pragma unroll
            for (int mt = 0; mt < 4; mt++) {
                const __half* sa = pa + (wm + mt * 16 + g) * PH + kb;
                af[mt][0] = *(const uint32_t*)(sa);
                af[mt][1] = *(const uint32_t*)(sa + 8 * PH);
                af[mt][2] = *(const uint32_t*)(sa + 8);
                af[mt][3] = *(const uint32_t*)(sa + 8 * PH + 8);
            }
#pragma unroll
            for (int nt = 0; nt < 4; nt++) {
                const __half* sb = pb + (wn + nt * 8 + g) * PH + kb;
                bf[nt][0] = *(const uint32_t*)(sb);
                bf[nt][1] = *(const uint32_t*)(sb + 8);
            }
#pragma unroll
            for (int mt = 0; mt < 4; mt++)
#pragma unroll
                for (int nt = 0; nt < 4; nt++)
                    mma_f16(acc[mt][nt], af[mt], bf[nt]);
        }
        __syncthreads();
        if (s + 2 < NS) LOAD_STAGE((s + 2) * KH, buf);
    }

    // epilogue: c0=[g][2t], c1=[g][2t+1], c2=[g+8][2t], c3=[g+8][2t+1]
#pragma unroll
    for (int nt = 0; nt < 4; nt++) {
        const int n0 = bn + wn + nt * 8 + 2 * t;
        float bb0 = 0.f, bb1 = 0.f;
        if (b1) { bb0 += b1[n0]; bb1 += b1[n0 + 1]; }
        if (b2) { bb0 += b2[n0]; bb1 += b2[n0 + 1]; }
#pragma unroll
        for (int mt = 0; mt < 4; mt++) {
            const int m0 = bm + wm + mt * 16 + g;
            float2 v0 = make_float2(acc[mt][nt][0] + bb0, acc[mt][nt][1] + bb1);
            float2 v1 = make_float2(acc[mt][nt][2] + bb0, acc[mt][nt][3] + bb1);
            *(float2*)(C + (size_t)m0 * N + n0)       = v0;
            *(float2*)(C + (size_t)(m0 + 8) * N + n0) = v1;
        }
    }
#undef LOAD_STAGE
}

// ---------------- fp32 -> fp16 conversion (vectorized) ----------------
__global__ void k_f2h(const float* __restrict__ src, __half* __restrict__ dst, int n4) {
    int i = blockIdx.x * blockDim.x + threadIdx.x;
    if (i < n4) {
        float4 v = ((const float4*)src)[i];
        ((__half2*)dst)[i*2 + 0] = __floats2half2_rn(v.x, v.y);
        ((__half2*)dst)[i*2 + 1] = __floats2half2_rn(v.z, v.w);
    }
}

// ---------------- init (zero h0, reset barriers) ----------------
__global__ void k_init() {
    int i = blockIdx.x * blockDim.x + threadIdx.x;
    if (i < 2*2*Bc*HHc) (&g_ench[0][0])[i] = 0.f;
    if (i < Bc*Tc)      g_xback[i] = 0;
    if (i < 4)          { g_cnt[i] = 0u; g_flag[i] = 0u; }
}

// ---------------- pad-aware reversed tokens ----------------
__global__ void k_xback(const int* __restrict__ x, const float* __restrict__ mask) {
    int b = threadIdx.x;
    if (b >= Bc) return;
    float s = 0.f;
    for (int t = 0; t < Tc; t++) s += mask[b*Tc + t];
    int pad = Tc - (int)(s + 0.5f);
    for (int j = 0; j < Tc; j++) {
        int r = Tc - 1 - j - pad;
        if (r < 0) r = 0;
        g_xback[b*Tc + r] = x[b*Tc + j];
    }
}

// ---------------- embedding gather -> fp16 ----------------
__global__ void k_gather_h(const int* __restrict__ idx, const float* __restrict__ embed,
                           __half* __restrict__ out) {
    int row = blockIdx.x;
    int e = threadIdx.x;                 // 128 threads, Ec/4 float4s
    float4 v = ((const float4*)(embed + (size_t)idx[row] * Ec))[e];
    ((__half2*)out)[(size_t)row * (Ec/2) + e*2 + 0] = __floats2half2_rn(v.x, v.y);
    ((__half2*)out)[(size_t)row * (Ec/2) + e*2 + 1] = __floats2half2_rn(v.z, v.w);
}

// ======================================================================
// Persistent encoder scan: 64 blocks (32 per direction), weights in smem,
// h ping-pong in global [u][b], c/hsum/csum in registers, per-dir barrier.
// ======================================================================
__global__ __launch_bounds__(256, 1)
void k_enc_scan(const float* __restrict__ whh_f, const float* __restrict__ whh_b) {
    extern __shared__ float sm[];
    float* wt = sm;                 // [256][32] transposed weights
    float* sh = sm + 256*32;        // [256][33] h staged [k][b]
    float* gb = sh + 256*33;        // [32][33] gates [col][b]

    const int tid  = threadIdx.x;
    const int dir  = blockIdx.x >> 5;
    const int ub   = blockIdx.x & 31;
    const int u0   = ub * 8;
    const float* whh = dir ? whh_b : whh_f;
    const float* pre = dir ? g_encpre_b : g_encpre_f;

    for (int j = tid; j < 32*256; j += 256) {
        int col = j & 31, k = j >> 5;
        int gg = col >> 3, uu = col & 7;
        wt[k*32 + col] = whh[(size_t)(gg*HHc + u0 + uu)*HHc + k];
    }

    const int lane = tid & 31;
    const int wy   = tid >> 5;
    const int c0   = wy * 4;
    const int cb   = tid & 31;
    const int cu   = tid >> 5;
    const int ug   = dir*HHc + u0 + cu;
    float creg = 0.f, hsum = 0.f, csum = 0.f;
    __syncthreads();

    for (int t = 0; t < Tc; t++) {
        const float* h_in = &g_ench[t & 1][dir * (Bc*HHc)];
#pragma unroll
        for (int i = 0; i < 8; i++) {
            int idx = tid + i * 256;
            float4 v = __ldcg((const float4*)h_in + idx);
            int j = idx * 4;
            int k = j >> 5, b = j & 31;
            sh[k*33 + b + 0] = v.x; sh[k*33 + b + 1] = v.y;
            sh[k*33 + b + 2] = v.z; sh[k*33 + b + 3] = v.w;
        }
        const float* pbt = pre + (size_t)(cb*Tc + t) * (4*HHc) + u0 + cu;
        float pf0 = pbt[0*HHc], pf1 = pbt[1*HHc], pf2 = pbt[2*HHc], pf3 = pbt[3*HHc];
        __syncthreads();

        float a0 = 0.f, a1 = 0.f, a2 = 0.f, a3 = 0.f;
#pragma unroll 8
        for (int k = 0; k < 256; k++) {
            float4 wv = *(const float4*)&wt[k*32 + c0];
            float hv = sh[k*33 + lane];
            a0 += wv.x * hv; a1 += wv.y * hv; a2 += wv.z * hv; a3 += wv.w * hv;
        }
        gb[(c0+0)*33 + lane] = a0;
        gb[(c0+1)*33 + lane] = a1;
        gb[(c0+2)*33 + lane] = a2;
        gb[(c0+3)*33 + lane] = a3;
        __syncthreads();

        float gi = gb[(0*8 + cu)*33 + cb] + pf0;
        float gf = gb[(1*8 + cu)*33 + cb] + pf1;
        float gc = gb[(2*8 + cu)*33 + cb] + pf2;
        float go = gb[(3*8 + cu)*33 + cb] + pf3;
        creg = sigm(gf) * creg + sigm(gi) * tanhf(gc);
        float hnew = sigm(go) * tanhf(creg);
        hsum += hnew; csum += creg;
        g_ench[(t+1) & 1][dir*(Bc*HHc) + (u0+cu)*32 + cb] = hnew;
        g_hiddens[(size_t)(cb*Tc + t)*Hc + ug] = hnew;

        gbar(dir, (unsigned)(t + 1), 32u);
    }

    g_dech[0][ug*32 + cb] = hsum * (1.0f / Tc);
    g_decc0[ug*32 + cb]   = csum * (1.0f / Tc);
}

// ======================================================================
// Persistent decoder scan: 64 blocks, weights + h stage in smem.
// ======================================================================
__global__ __launch_bounds__(256, 1)
void k_dec_scan(const float* __restrict__ whh) {
    extern __shared__ float sm[];
    float* wt = sm;                 // [512][32]
    float* sh = sm + 512*32;        // [512][33]
    float* gb = sh + 512*33;        // [32][33]

    const int tid  = threadIdx.x;
    const int u0   = blockIdx.x * 8;

    for (int j = tid; j < 32*512; j += 256) {
        int col = j & 31, k = j >> 5;
        int gg = col >> 3, uu = col & 7;
        wt[k*32 + col] = whh[(size_t)(gg*Hc + u0 + uu)*Hc + k];
    }

    const int lane = tid & 31;
    const int wy   = tid >> 5;
    const int c0   = wy * 4;
    const int cb   = tid & 31;
    const int cu   = tid >> 5;
    float creg;
    __syncthreads();
    creg = g_decc0[(u0+cu)*32 + cb];

    for (int ty = 0; ty < TYc; ty++) {
        const float* h_in = &g_dech[ty & 1][0];
#pragma unroll
        for (int i = 0; i < 16; i++) {
            int idx = tid + i * 256;
            float4 v = __ldcg((const float4*)h_in + idx);
            int j = idx * 4;
            int k = j >> 5, b = j & 31;
            sh[k*33 + b + 0] = v.x; sh[k*33 + b + 1] = v.y;
            sh[k*33 + b + 2] = v.z; sh[k*33 + b + 3] = v.w;
        }
        const float* pbt = g_decpre + (size_t)(cb*TYc + ty) * (4*Hc) + u0 + cu;
        float pf0 = pbt[0*Hc], pf1 = pbt[1*Hc], pf2 = pbt[2*Hc], pf3 = pbt[3*Hc];
        __syncthreads();

        float a0 = 0.f, a1 = 0.f, a2 = 0.f, a3 = 0.f;
#pragma unroll 8
        for (int k = 0; k < 512; k++) {
            float4 wv = *(const float4*)&wt[k*32 + c0];
            float hv = sh[k*33 + lane];
            a0 += wv.x * hv; a1 += wv.y * hv; a2 += wv.z * hv; a3 += wv.w * hv;
        }
        gb[(c0+0)*33 + lane] = a0;
        gb[(c0+1)*33 + lane] = a1;
        gb[(c0+2)*33 + lane] = a2;
        gb[(c0+3)*33 + lane] = a3;
        __syncthreads();

        float gi = gb[(0*8 + cu)*33 + cb] + pf0;
        float gf = gb[(1*8 + cu)*33 + cb] + pf1;
        float gc = gb[(2*8 + cu)*33 + cb] + pf2;
        float go = gb[(3*8 + cu)*33 + cb] + pf3;
        creg = sigm(gf) * creg + sigm(gi) * tanhf(gc);
        float hnew = sigm(go) * tanhf(creg);
        g_dech[(ty+1) & 1][(u0+cu)*32 + cb] = hnew;
        g_outhid[(size_t)(cb*TYc + ty)*(2*Hc) + u0 + cu] = hnew;

        gbar(2, (unsigned)(ty + 1), 64u);
    }
}

// ---------------- attention, batch-parallel over (b, ty) ----------------
__global__ __launch_bounds__(256, 1)
void k_attn() {
    const int b  = blockIdx.x;
    const int ty = blockIdx.y;
    const float* h = g_outhid + (size_t)(b*TYc + ty)*(2*Hc);
    __shared__ float hs[Hc];
    __shared__ float sc[Tc];
    __shared__ float red[8];
    for (int i = threadIdx.x; i < Hc; i += 256) hs[i] = h[i];
    __syncthreads();

    const int tp = threadIdx.x >> 1;
    const int half = threadIdx.x & 1;
    const float* hid = g_hiddens + (size_t)(b*Tc + tp)*Hc + half*256;
    const float* hq = hs + half*256;
    float s = 0.f;
#pragma unroll 4
    for (int k = 0; k < 256; k += 4) {
        float4 a = *(const float4*)(hid + k);
        float4 c = *(const float4*)(hq + k);
        s += a.x*c.x + a.y*c.y + a.z*c.z + a.w*c.w;
    }
    s += __shfl_down_sync(0xffffffffu, s, 1);
    if (half == 0) sc[tp] = s;
    __syncthreads();

    const int lane = threadIdx.x & 31, wid = threadIdx.x >> 5;
    float v = (threadIdx.x < Tc) ? sc[threadIdx.x] : -1e30f;
    float m = v;
    for (int o = 16; o; o >>= 1) m = fmaxf(m, __shfl_xor_sync(0xffffffffu, m, o));
    if (!lane) red[wid] = m;
    __syncthreads();
    if (!wid) {
        float xx = (lane < 8) ? red[lane] : -1e30f;
        for (int o = 4; o; o >>= 1) xx = fmaxf(xx, __shfl_xor_sync(0xffffffffu, xx, o));
        if (!lane) red[0] = xx;
    }
    __syncthreads();
    m = red[0];
    float e = (threadIdx.x < Tc) ? expf(v - m) : 0.f;
    float ssum = e;
    for (int o = 16; o; o >>= 1) ssum += __shfl_xor_sync(0xffffffffu, ssum, o);
    __syncthreads();
    if (!lane) red[wid] = ssum;
    __syncthreads();
    if (!wid) {
        float xx = (lane < 8) ? red[lane] : 0.f;
        for (int o = 4; o; o >>= 1) xx += __shfl_xor_sync(0xffffffffu, xx, o);
        if (!lane) red[0] = xx;
    }
    __syncthreads();
    float inv = 1.f / red[0];
    if (threadIdx.x < Tc) sc[threadIdx.x] = e * inv;
    __syncthreads();

    float* octx = g_outhid + (size_t)(b*TYc + ty)*(2*Hc) + Hc;
    for (int d = threadIdx.x; d < Hc; d += 256) {
        float a = 0.f;
#pragma unroll 8
        for (int tq = 0; tq < Tc; tq++) a += sc[tq] * g_hiddens[(size_t)(b*Tc + tq)*Hc + d];
        octx[d] = a;
    }
}

// ---------------- in-place log_softmax (fused online max+sum: 2 passes) ----------------
__global__ __launch_bounds__(256)
void k_logsoftmax(float* __restrict__ out) {
    const int row = blockIdx.x;
    float* p = out + (size_t)row * Vc;
    __shared__ float redm[8], reds[8];
    const int lane = threadIdx.x & 31, wid = threadIdx.x >> 5;

    float m = -1e30f, s = 0.f;
    for (int i = threadIdx.x; i < Vc; i += 256) {
        float v = p[i];
        if (v > m) { s = s * expf(m - v) + 1.f; m = v; }
        else       s += expf(v - m);
    }
    for (int o = 16; o; o >>= 1) {
        float mo = __shfl_xor_sync(0xffffffffu, m, o);
        float so = __shfl_xor_sync(0xffffffffu, s, o);
        float mn = fmaxf(m, mo);
        s = s * expf(m - mn) + so * expf(mo - mn);
        m = mn;
    }
    if (!lane) { redm[wid] = m; reds[wid] = s; }
    __syncthreads();
    if (!wid) {
        float mm = (lane < 8) ? redm[lane] : -1e30f;
        float ss = (lane < 8) ? reds[lane] : 0.f;
        for (int o = 4; o; o >>= 1) {
            float mo = __shfl_xor_sync(0xffffffffu, mm, o);
            float so = __shfl_xor_sync(0xffffffffu, ss, o);
            float mn = fmaxf(mm, mo);
            ss = ss * expf(mm - mn) + so * expf(mo - mn);
            mm = mn;
        }
        if (!lane) { redm[0] = mm; reds[0] = ss; }
    }
    __syncthreads();
    float lse = redm[0] + logf(reds[0]);
    for (int i = threadIdx.x; i < Vc; i += 256) p[i] -= lse;
}

__global__ void k_copy_tail(float* __restrict__ dst) {
    int i = blockIdx.x * blockDim.x + threadIdx.x;
    if (i < Bc*TYc*2*Hc) dst[i] = g_outhid[i];
}

// ---------------- launch ----------------
extern "C" void kernel_launch(void* const* d_in, const int* in_sizes, int n_in,
                              void* d_out, int out_size) {
    (void)in_sizes; (void)n_in;
    const int*   x      = (const int*)  d_in[0];
    const float* xmask  = (const float*)d_in[1];
    const int*   y      = (const int*)  d_in[2];
    const float* embed  = (const float*)d_in[3];
    const float* w_ih_f = (const float*)d_in[4];
    const float* w_hh_f = (const float*)d_in[5];
    const float* b_ih_f = (const float*)d_in[6];
    const float* b_hh_f = (const float*)d_in[7];
    const float* w_ih_b = (const float*)d_in[8];
    const float* w_hh_b = (const float*)d_in[9];
    const float* b_ih_b = (const float*)d_in[10];
    const float* b_hh_b = (const float*)d_in[11];
    const float* w_ih_d = (const float*)d_in[12];
    const float* w_hh_d = (const float*)d_in[13];
    const float* b_ih_d = (const float*)d_in[14];
    const float* b_hh_d = (const float*)d_in[15];
    const float* W_out  = (const float*)d_in[16];
    const float* b_out  = (const float*)d_in[17];
    float* out = (float*)d_out;

    void *p_xembh, *p_xbembh, *p_yembh, *p_pref, *p_preb, *p_decpre, *p_outhid, *p_outhidh, *p_xback;
    void *p_wf, *p_wb, *p_wd, *p_Wo;
    cudaGetSymbolAddress(&p_xembh,  g_xembh);
    cudaGetSymbolAddress(&p_xbembh, g_xbembh);
    cudaGetSymbolAddress(&p_yembh,  g_yembh);
    cudaGetSymbolAddress(&p_pref,   g_encpre_f);
    cudaGetSymbolAddress(&p_preb,   g_encpre_b);
    cudaGetSymbolAddress(&p_decpre, g_decpre);
    cudaGetSymbolAddress(&p_outhid, g_outhid);
    cudaGetSymbolAddress(&p_outhidh,g_outhidh);
    cudaGetSymbolAddress(&p_xback,  g_xback);
    cudaGetSymbolAddress(&p_wf,     g_wihf_h);
    cudaGetSymbolAddress(&p_wb,     g_wihb_h);
    cudaGetSymbolAddress(&p_wd,     g_wihd_h);
    cudaGetSymbolAddress(&p_Wo,     g_Wouth);

    const int ENC_SMEM = (256*32 + 256*33 + 32*33) * 4;   //  70784 B
    const int DEC_SMEM = (512*32 + 512*33 + 32*33) * 4;   // 137344 B
    static bool attr_done = false;
    if (!attr_done) {
        cudaFuncSetAttribute(k_enc_scan, cudaFuncAttributeMaxDynamicSharedMemorySize, ENC_SMEM);
        cudaFuncSetAttribute(k_dec_scan, cudaFuncAttributeMaxDynamicSharedMemorySize, DEC_SMEM);
        attr_done = true;
    }

    k_init<<<128, 256>>>();
    k_xback<<<1, 32>>>(x, xmask);

    // weight conversions (fp32 -> fp16)
    k_f2h<<<(4*HHc*Ec/4 + 255)/256, 256>>>(w_ih_f, (__half*)p_wf, 4*HHc*Ec/4);
    k_f2h<<<(4*HHc*Ec/4 + 255)/256, 256>>>(w_ih_b, (__half*)p_wb, 4*HHc*Ec/4);
    k_f2h<<<(4*Hc*Ec/4  + 255)/256, 256>>>(w_ih_d, (__half*)p_wd, 4*Hc*Ec/4);
    k_f2h<<<(Vc*2*Hc/4  + 255)/256, 256>>>(W_out,  (__half*)p_Wo, Vc*2*Hc/4);

    k_gather_h<<<Bc*Tc, 128>>>(x, embed, (__half*)p_xembh);
    k_gather_h<<<Bc*Tc, 128>>>((const int*)p_xback, embed, (__half*)p_xbembh);
    k_gather_h<<<Bc*TYc, 128>>>(y, embed, (__half*)p_yembh);

    // time-batched input-side GEMMs (fp16 mma), fold both biases
    k_hmma<<<dim3((Bc*Tc)/128, (4*HHc)/128), 256>>>(
        (const __half*)p_xembh,  (const __half*)p_wf, b_ih_f, b_hh_f, (float*)p_pref,   Bc*Tc,  4*HHc, Ec);
    k_hmma<<<dim3((Bc*Tc)/128, (4*HHc)/128), 256>>>(
        (const __half*)p_xbembh, (const __half*)p_wb, b_ih_b, b_hh_b, (float*)p_preb,   Bc*Tc,  4*HHc, Ec);
    k_hmma<<<dim3((Bc*TYc)/128, (4*Hc)/128), 256>>>(
        (const __half*)p_yembh,  (const __half*)p_wd, b_ih_d, b_hh_d, (float*)p_decpre, Bc*TYc, 4*Hc,  Ec);

    // persistent scans (software grid barriers; 64 blocks <= SM count)
    k_enc_scan<<<64, 256, ENC_SMEM>>>(w_hh_f, w_hh_b);
    k_dec_scan<<<64, 256, DEC_SMEM>>>(w_hh_d);

    // attention, fully parallel over (b, ty)
    k_attn<<<dim3(Bc, TYc), 256>>>();

    // outhid -> fp16, then projection + log_softmax
    k_f2h<<<(Bc*TYc*2*Hc/4 + 255)/256, 256>>>((const float*)p_outhid, (__half*)p_outhidh, Bc*TYc*2*Hc/4);
    k_hmma<<<dim3((Bc*TYc)/128, Vc/128), 256>>>(
        (const __half*)p_outhidh, (const __half*)p_Wo, b_out, nullptr, out, Bc*TYc, Vc, 2*Hc);
    k_logsoftmax<<<Bc*TYc, 256>>>(out);

    long long need = (long long)Bc*TYc*Vc + (long long)Bc*TYc*2*Hc;
    if ((long long)out_size >= need)
        k_copy_tail<<<(Bc*TYc*2*Hc + 255)/256, 256>>>(out + (size_t)Bc*TYc*Vc);
}

// round 10
// speedup vs baseline: 4.3108x; 1.1806x over previous
#include <cuda_runtime.h>
#include <cuda_fp16.h>
#include <math.h>
#include <stdint.h>

// Problem dims
#define Bc  32
#define Tc  128
#define TYc 64
#define Ec  512
#define Hc  512
#define HHc 256
#define Vc  32000

// ---------------- scratch (__device__ globals; no allocations) ----------------
__device__ __half g_xembh [Bc*Tc*Ec];
__device__ __half g_xbembh[Bc*Tc*Ec];
__device__ __half g_yembh [Bc*TYc*Ec];
__device__ int    g_xback [Bc*Tc];
__device__ float  g_encpre_f[Bc*Tc*4*HHc];
__device__ float  g_encpre_b[Bc*Tc*4*HHc];
__device__ float  g_decpre  [Bc*TYc*4*Hc];
__device__ float  g_ench[2][2*Bc*HHc];   // ping-pong h, [pp][dir*8192 + u*32 + b]
__device__ float  g_hiddens[Bc*Tc*Hc];   // [b][t][fwd|bwd]
__device__ float  g_dech[2][Bc*Hc];      // ping-pong decoder h, [pp][u*32 + b]
__device__ float  g_decc0[Bc*Hc];        // decoder c init, [u*32 + b]
__device__ float  g_outhid[Bc*TYc*2*Hc]; // [b][ty][h|ctx] fp32 (for tail copy)
__device__ __half g_outhidh[Bc*TYc*2*Hc];
// fp16 weight copies
__device__ __half g_wihf_h[4*HHc*Ec];
__device__ __half g_wihb_h[4*HHc*Ec];
__device__ __half g_wihd_h[4*Hc*Ec];
__device__ __half g_Wouth [Vc*2*Hc];

// software grid barrier state (reset by k_init every replay)
__device__ unsigned g_cnt[4];
__device__ volatile unsigned g_flag[4];

__device__ __forceinline__ float sigm(float x) { return 1.f / (1.f + expf(-x)); }

__device__ __forceinline__ void gbar(int idx, unsigned phase, unsigned nb) {
    __syncthreads();
    if (threadIdx.x == 0) {
        __threadfence();
        unsigned old = atomicAdd(&g_cnt[idx], 1u);
        if (old == phase * nb - 1u) g_flag[idx] = phase;
        else while (g_flag[idx] < phase) { }
    }
    __syncthreads();
}

__device__ __forceinline__ uint32_t smem_u32(const void* p) {
    uint32_t a;
    asm("{ .reg .u64 t; cvta.to.shared.u64 t, %1; cvt.u32.u64 %0, t; }" : "=r"(a) : "l"(p));
    return a;
}
__device__ __forceinline__ void ldsm_x4(uint32_t* r, uint32_t addr) {
    asm volatile("ldmatrix.sync.aligned.m8n8.x4.shared.b16 {%0,%1,%2,%3}, [%4];"
        : "=r"(r[0]), "=r"(r[1]), "=r"(r[2]), "=r"(r[3]) : "r"(addr));
}
__device__ __forceinline__ void ldsm_x2(uint32_t* r, uint32_t addr) {
    asm volatile("ldmatrix.sync.aligned.m8n8.x2.shared.b16 {%0,%1}, [%2];"
        : "=r"(r[0]), "=r"(r[1]) : "r"(addr));
}

// ======================================================================
// fp16 mma.sync GEMM: C[M,N] = A[M,K] @ W[N,K]^T (+b1[n] +b2[n]), fp32 accum
// CTA tile 128x128, 8 warps, warp tile 64x32, K-stage 32 halves, cp.async x2,
// ldmatrix fragment loads. Pitch 40 halves = 80B (16B-aligned; ldmatrix
// 8-row phases hit disjoint bank sets: row*20 mod 32 all distinct).
// ======================================================================
#define KH 32
#define PH 40

__device__ __forceinline__ void mma_f16(float* d, const uint32_t* a, const uint32_t* b) {
    asm volatile(
        "mma.sync.aligned.m16n8k16.row.col.f32.f16.f16.f32 "
        "{%0,%1,%2,%3}, {%4,%5,%6,%7}, {%8,%9}, {%0,%1,%2,%3};\n"
        : "+f"(d[0]), "+f"(d[1]), "+f"(d[2]), "+f"(d[3])
        : "r"(a[0]), "r"(a[1]), "r"(a[2]), "r"(a[3]), "r"(b[0]), "r"(b[1]));
}

__global__ __launch_bounds__(256, 2)
void k_hmma(const __half* __restrict__ A, const __half* __restrict__ W,
            const float* __restrict__ b1, const float* __restrict__ b2,
            float* __restrict__ C, int M, int N, int K) {
    __shared__ __half sA[2][128 * PH];
    __shared__ __half sB[2][128 * PH];

    const int tid  = threadIdx.x;
    const int wid  = tid >> 5;
    const int lane = tid & 31;
    const int g    = lane >> 2;
    const int t    = lane & 3;
    const int wm   = (wid & 1) * 64;
    const int wn   = (wid >> 1) * 32;
    const int bm   = blockIdx.x * 128;
    const int bn   = blockIdx.y * 128;

    const __half* Ab = A + (size_t)bm * K;
    const __half* Wb = W + (size_t)bn * K;

    // ldmatrix per-lane byte offsets (within a stage buffer)
    const uint32_t aoff = ((wm + (lane & 15)) * PH + (lane >> 4) * 8) * 2;
    const uint32_t boff = ((wn + (lane & 7)) * PH + ((lane >> 3) & 1) * 8) * 2;
    const uint32_t sA0 = smem_u32(&sA[0][0]), sA1 = smem_u32(&sA[1][0]);
    const uint32_t sB0 = smem_u32(&sB[0][0]), sB1 = smem_u32(&sB[1][0]);

#define LOAD_STAGE(KC0, S) do { \
    _Pragma("unroll") \
    for (int _i = 0; _i < 2; _i++) { \
        int _idx = tid + _i * 256; \
        int _row = _idx >> 2, _seg = _idx & 3; \
        uint32_t _da; \
        asm("{ .reg .u64 t; cvta.to.shared.u64 t, %1; cvt.u32.u64 %0, t; }" \
            : "=r"(_da) : "l"(&sA[S][_row * PH + _seg * 8])); \
        const __half* _sa = Ab + (size_t)_row * K + (KC0) + _seg * 8; \
        asm volatile("cp.async.cg.shared.global [%0], [%1], 16;" :: "r"(_da), "l"(_sa)); \
        uint32_t _db; \
        asm("{ .reg .u64 t; cvta.to.shared.u64 t, %1; cvt.u32.u64 %0, t; }" \
            : "=r"(_db) : "l"(&sB[S][_row * PH + _seg * 8])); \
        const __half* _sb = Wb + (size_t)_row * K + (KC0) + _seg * 8; \
        asm volatile("cp.async.cg.shared.global [%0], [%1], 16;" :: "r"(_db), "l"(_sb)); \
    } \
    asm volatile("cp.async.commit_group;" ::: "memory"); \
} while (0)

    float acc[4][4][4];
#pragma unroll
    for (int i = 0; i < 4; i++)
#pragma unroll
        for (int j = 0; j < 4; j++)
#pragma unroll
            for (int r = 0; r < 4; r++) acc[i][j][r] = 0.f;

    const int NS = K / KH;
    LOAD_STAGE(0, 0);
    LOAD_STAGE(KH, 1);

    for (int s = 0; s < NS; s++) {
        if (s + 1 < NS) asm volatile("cp.async.wait_group 1;" ::: "memory");
        else            asm volatile("cp.async.wait_group 0;" ::: "memory");
        __syncthreads();
        const int buf = s & 1;
        const uint32_t pa = (buf ? sA1 : sA0) + aoff;
        const uint32_t pb = (buf ? sB1 : sB0) + boff;
#pragma unroll
        for (int ks = 0; ks < 2; ks++) {
            const uint32_t ko = ks * 32;      // 16 halves = 32B
            uint32_t af[4][4], bf[4][2];
#pragma unroll
            for (int mt = 0; mt < 4; mt++)
                ldsm_x4(af[mt], pa + mt * (16 * PH * 2) + ko);
#pragma unroll
            for (int nt = 0; nt < 4; nt++)
                ldsm_x2(bf[nt], pb + nt * (8 * PH * 2) + ko);
#pragma unroll
            for (int mt = 0; mt < 4; mt++)
#pragma unroll
                for (int nt = 0; nt < 4; nt++)
                    mma_f16(acc[mt][nt], af[mt], bf[nt]);
        }
        __syncthreads();
        if (s + 2 < NS) LOAD_STAGE((s + 2) * KH, buf);
    }

    // epilogue: c0=[g][2t], c1=[g][2t+1], c2=[g+8][2t], c3=[g+8][2t+1]
#pragma unroll
    for (int nt = 0; nt < 4; nt++) {
        const int n0 = bn + wn + nt * 8 + 2 * t;
        float bb0 = 0.f, bb1 = 0.f;
        if (b1) { bb0 += b1[n0]; bb1 += b1[n0 + 1]; }
        if (b2) { bb0 += b2[n0]; bb1 += b2[n0 + 1]; }
#pragma unroll
        for (int mt = 0; mt < 4; mt++) {
            const int m0 = bm + wm + mt * 16 + g;
            float2 v0 = make_float2(acc[mt][nt][0] + bb0, acc[mt][nt][1] + bb1);
            float2 v1 = make_float2(acc[mt][nt][2] + bb0, acc[mt][nt][3] + bb1);
            *(float2*)(C + (size_t)m0 * N + n0)       = v0;
            *(float2*)(C + (size_t)(m0 + 8) * N + n0) = v1;
        }
    }
#undef LOAD_STAGE
}

// ---------------- fp32 -> fp16 conversion (vectorized) ----------------
__global__ void k_f2h(const float* __restrict__ src, __half* __restrict__ dst, int n4) {
    int i = blockIdx.x * blockDim.x + threadIdx.x;
    if (i < n4) {
        float4 v = ((const float4*)src)[i];
        ((__half2*)dst)[i*2 + 0] = __floats2half2_rn(v.x, v.y);
        ((__half2*)dst)[i*2 + 1] = __floats2half2_rn(v.z, v.w);
    }
}

// ---------------- init (zero h0, reset barriers) ----------------
__global__ void k_init() {
    int i = blockIdx.x * blockDim.x + threadIdx.x;
    if (i < 2*2*Bc*HHc) (&g_ench[0][0])[i] = 0.f;
    if (i < Bc*Tc)      g_xback[i] = 0;
    if (i < 4)          { g_cnt[i] = 0u; g_flag[i] = 0u; }
}

// ---------------- pad-aware reversed tokens ----------------
__global__ void k_xback(const int* __restrict__ x, const float* __restrict__ mask) {
    int b = threadIdx.x;
    if (b >= Bc) return;
    float s = 0.f;
    for (int t = 0; t < Tc; t++) s += mask[b*Tc + t];
    int pad = Tc - (int)(s + 0.5f);
    for (int j = 0; j < Tc; j++) {
        int r = Tc - 1 - j - pad;
        if (r < 0) r = 0;
        g_xback[b*Tc + r] = x[b*Tc + j];
    }
}

// ---------------- embedding gather -> fp16 ----------------
__global__ void k_gather_h(const int* __restrict__ idx, const float* __restrict__ embed,
                           __half* __restrict__ out) {
    int row = blockIdx.x;
    int e = threadIdx.x;
    float4 v = ((const float4*)(embed + (size_t)idx[row] * Ec))[e];
    ((__half2*)out)[(size_t)row * (Ec/2) + e*2 + 0] = __floats2half2_rn(v.x, v.y);
    ((__half2*)out)[(size_t)row * (Ec/2) + e*2 + 1] = __floats2half2_rn(v.z, v.w);
}

// ======================================================================
// Persistent encoder scan: 128 blocks (64 per direction, 4 units each).
// Inner loop: LDS.64(w) + LDS.32(h) + 2 FFMA per k.
// ======================================================================
__global__ __launch_bounds__(256, 1)
void k_enc_scan(const float* __restrict__ whh_f, const float* __restrict__ whh_b) {
    extern __shared__ float sm[];
    float* wt = sm;                 // [256][16]  (4 gates x 4 units)
    float* sh = sm + 256*16;        // [256][33]  h staged [k][b]
    float* gb = sh + 256*33;        // [16][33]   gates [col][b]

    const int tid  = threadIdx.x;
    const int dir  = blockIdx.x >> 6;
    const int ub   = blockIdx.x & 63;
    const int u0   = ub * 4;
    const float* whh = dir ? whh_b : whh_f;
    const float* pre = dir ? g_encpre_b : g_encpre_f;

    // wt[k][col], col = gate*4 + uu
    for (int j = tid; j < 16*256; j += 256) {
        int col = j & 15, k = j >> 4;
        int gg = col >> 2, uu = col & 3;
        wt[k*16 + col] = whh[(size_t)(gg*HHc + u0 + uu)*HHc + k];
    }

    const int lane = tid & 31;
    const int c0   = (tid >> 5) * 2;     // 2 cols per thread, batch = lane
    const int cb   = tid & 31;           // cell: batch
    const int cu   = tid >> 5;           // cell: unit 0..3 (tid<128 active)
    const bool act = tid < 128;
    const int ug   = dir*HHc + u0 + (act ? cu : 0);
    float creg = 0.f, hsum = 0.f, csum = 0.f;
    __syncthreads();

    for (int t = 0; t < Tc; t++) {
        const float* h_in = &g_ench[t & 1][dir * (Bc*HHc)];
#pragma unroll
        for (int i = 0; i < 8; i++) {
            int idx = tid + i * 256;
            float4 v = __ldcg((const float4*)h_in + idx);
            int j = idx * 4;
            int k = j >> 5, b = j & 31;
            sh[k*33 + b + 0] = v.x; sh[k*33 + b + 1] = v.y;
            sh[k*33 + b + 2] = v.z; sh[k*33 + b + 3] = v.w;
        }
        float pf0 = 0.f, pf1 = 0.f, pf2 = 0.f, pf3 = 0.f;
        if (act) {
            const float* pbt = pre + (size_t)(cb*Tc + t) * (4*HHc) + u0 + cu;
            pf0 = pbt[0*HHc]; pf1 = pbt[1*HHc]; pf2 = pbt[2*HHc]; pf3 = pbt[3*HHc];
        }
        __syncthreads();

        float a0 = 0.f, a1 = 0.f;
#pragma unroll 8
        for (int k = 0; k < 256; k++) {
            float2 w2 = *(const float2*)&wt[k*16 + c0];
            float hv = sh[k*33 + lane];
            a0 += w2.x * hv; a1 += w2.y * hv;
        }
        gb[(c0+0)*33 + lane] = a0;
        gb[(c0+1)*33 + lane] = a1;
        __syncthreads();

        if (act) {
            float gi = gb[(0*4 + cu)*33 + cb] + pf0;
            float gf = gb[(1*4 + cu)*33 + cb] + pf1;
            float gc = gb[(2*4 + cu)*33 + cb] + pf2;
            float go = gb[(3*4 + cu)*33 + cb] + pf3;
            creg = sigm(gf) * creg + sigm(gi) * tanhf(gc);
            float hnew = sigm(go) * tanhf(creg);
            hsum += hnew; csum += creg;
            g_ench[(t+1) & 1][dir*(Bc*HHc) + (u0+cu)*32 + cb] = hnew;
            g_hiddens[(size_t)(cb*Tc + t)*Hc + ug] = hnew;
        }
        gbar(dir, (unsigned)(t + 1), 64u);
    }

    if (act) {
        g_dech[0][ug*32 + cb] = hsum * (1.0f / Tc);
        g_decc0[ug*32 + cb]   = csum * (1.0f / Tc);
    }
}

// ======================================================================
// Persistent decoder scan: 128 blocks, 4 units each.
// ======================================================================
__global__ __launch_bounds__(256, 1)
void k_dec_scan(const float* __restrict__ whh) {
    extern __shared__ float sm[];
    float* wt = sm;                 // [512][16]
    float* sh = sm + 512*16;        // [512][33]
    float* gb = sh + 512*33;        // [16][33]

    const int tid  = threadIdx.x;
    const int u0   = blockIdx.x * 4;

    for (int j = tid; j < 16*512; j += 256) {
        int col = j & 15, k = j >> 4;
        int gg = col >> 2, uu = col & 3;
        wt[k*16 + col] = whh[(size_t)(gg*Hc + u0 + uu)*Hc + k];
    }

    const int lane = tid & 31;
    const int c0   = (tid >> 5) * 2;
    const int cb   = tid & 31;
    const int cu   = tid >> 5;
    const bool act = tid < 128;
    float creg = 0.f;
    __syncthreads();
    if (act) creg = g_decc0[(u0+cu)*32 + cb];

    for (int ty = 0; ty < TYc; ty++) {
        const float* h_in = &g_dech[ty & 1][0];
#pragma unroll
        for (int i = 0; i < 16; i++) {
            int idx = tid + i * 256;
            float4 v = __ldcg((const float4*)h_in + idx);
            int j = idx * 4;
            int k = j >> 5, b = j & 31;
            sh[k*33 + b + 0] = v.x; sh[k*33 + b + 1] = v.y;
            sh[k*33 + b + 2] = v.z; sh[k*33 + b + 3] = v.w;
        }
        float pf0 = 0.f, pf1 = 0.f, pf2 = 0.f, pf3 = 0.f;
        if (act) {
            const float* pbt = g_decpre + (size_t)(cb*TYc + ty) * (4*Hc) + u0 + cu;
            pf0 = pbt[0*Hc]; pf1 = pbt[1*Hc]; pf2 = pbt[2*Hc]; pf3 = pbt[3*Hc];
        }
        __syncthreads();

        float a0 = 0.f, a1 = 0.f;
#pragma unroll 8
        for (int k = 0; k < 512; k++) {
            float2 w2 = *(const float2*)&wt[k*16 + c0];
            float hv = sh[k*33 + lane];
            a0 += w2.x * hv; a1 += w2.y * hv;
        }
        gb[(c0+0)*33 + lane] = a0;
        gb[(c0+1)*33 + lane] = a1;
        __syncthreads();

        if (act) {
            float gi = gb[(0*4 + cu)*33 + cb] + pf0;
            float gf = gb[(1*4 + cu)*33 + cb] + pf1;
            float gc = gb[(2*4 + cu)*33 + cb] + pf2;
            float go = gb[(3*4 + cu)*33 + cb] + pf3;
            creg = sigm(gf) * creg + sigm(gi) * tanhf(gc);
            float hnew = sigm(go) * tanhf(creg);
            g_dech[(ty+1) & 1][(u0+cu)*32 + cb] = hnew;
            size_t oi = (size_t)(cb*TYc + ty)*(2*Hc) + u0 + cu;
            g_outhid[oi]  = hnew;
            g_outhidh[oi] = __float2half(hnew);
        }
        gbar(2, (unsigned)(ty + 1), 128u);
    }
}

// ---------------- attention, batch-parallel over (b, ty) ----------------
__global__ __launch_bounds__(256, 1)
void k_attn() {
    const int b  = blockIdx.x;
    const int ty = blockIdx.y;
    const float* h = g_outhid + (size_t)(b*TYc + ty)*(2*Hc);
    __shared__ float hs[Hc];
    __shared__ float sc[Tc];
    __shared__ float red[8];
    for (int i = threadIdx.x; i < Hc; i += 256) hs[i] = h[i];
    __syncthreads();

    const int tp = threadIdx.x >> 1;
    const int half = threadIdx.x & 1;
    const float* hid = g_hiddens + (size_t)(b*Tc + tp)*Hc + half*256;
    const float* hq = hs + half*256;
    float s = 0.f;
#pragma unroll 4
    for (int k = 0; k < 256; k += 4) {
        float4 a = *(const float4*)(hid + k);
        float4 c = *(const float4*)(hq + k);
        s += a.x*c.x + a.y*c.y + a.z*c.z + a.w*c.w;
    }
    s += __shfl_down_sync(0xffffffffu, s, 1);
    if (half == 0) sc[tp] = s;
    __syncthreads();

    const int lane = threadIdx.x & 31, wid = threadIdx.x >> 5;
    float v = (threadIdx.x < Tc) ? sc[threadIdx.x] : -1e30f;
    float m = v;
    for (int o = 16; o; o >>= 1) m = fmaxf(m, __shfl_xor_sync(0xffffffffu, m, o));
    if (!lane) red[wid] = m;
    __syncthreads();
    if (!wid) {
        float xx = (lane < 8) ? red[lane] : -1e30f;
        for (int o = 4; o; o >>= 1) xx = fmaxf(xx, __shfl_xor_sync(0xffffffffu, xx, o));
        if (!lane) red[0] = xx;
    }
    __syncthreads();
    m = red[0];
    float e = (threadIdx.x < Tc) ? expf(v - m) : 0.f;
    float ssum = e;
    for (int o = 16; o; o >>= 1) ssum += __shfl_xor_sync(0xffffffffu, ssum, o);
    __syncthreads();
    if (!lane) red[wid] = ssum;
    __syncthreads();
    if (!wid) {
        float xx = (lane < 8) ? red[lane] : 0.f;
        for (int o = 4; o; o >>= 1) xx += __shfl_xor_sync(0xffffffffu, xx, o);
        if (!lane) red[0] = xx;
    }
    __syncthreads();
    float inv = 1.f / red[0];
    if (threadIdx.x < Tc) sc[threadIdx.x] = e * inv;
    __syncthreads();

    float* octx  = g_outhid  + (size_t)(b*TYc + ty)*(2*Hc) + Hc;
    __half* octh = g_outhidh + (size_t)(b*TYc + ty)*(2*Hc) + Hc;
    for (int d = threadIdx.x; d < Hc; d += 256) {
        float a = 0.f;
#pragma unroll 8
        for (int tq = 0; tq < Tc; tq++) a += sc[tq] * g_hiddens[(size_t)(b*Tc + tq)*Hc + d];
        octx[d] = a;
        octh[d] = __float2half(a);
    }
}

// ---------------- in-place log_softmax (online max+sum: 2 passes) ----------------
__global__ __launch_bounds__(256)
void k_logsoftmax(float* __restrict__ out) {
    const int row = blockIdx.x;
    float* p = out + (size_t)row * Vc;
    __shared__ float redm[8], reds[8];
    const int lane = threadIdx.x & 31, wid = threadIdx.x >> 5;

    float m = -1e30f, s = 0.f;
    for (int i = threadIdx.x; i < Vc; i += 256) {
        float v = p[i];
        if (v > m) { s = s * expf(m - v) + 1.f; m = v; }
        else       s += expf(v - m);
    }
    for (int o = 16; o; o >>= 1) {
        float mo = __shfl_xor_sync(0xffffffffu, m, o);
        float so = __shfl_xor_sync(0xffffffffu, s, o);
        float mn = fmaxf(m, mo);
        s = s * expf(m - mn) + so * expf(mo - mn);
        m = mn;
    }
    if (!lane) { redm[wid] = m; reds[wid] = s; }
    __syncthreads();
    if (!wid) {
        float mm = (lane < 8) ? redm[lane] : -1e30f;
        float ss = (lane < 8) ? reds[lane] : 0.f;
        for (int o = 4; o; o >>= 1) {
            float mo = __shfl_xor_sync(0xffffffffu, mm, o);
            float so = __shfl_xor_sync(0xffffffffu, ss, o);
            float mn = fmaxf(mm, mo);
            ss = ss * expf(mm - mn) + so * expf(mo - mn);
            mm = mn;
        }
        if (!lane) { redm[0] = mm; reds[0] = ss; }
    }
    __syncthreads();
    float lse = redm[0] + logf(reds[0]);
    for (int i = threadIdx.x; i < Vc; i += 256) p[i] -= lse;
}

__global__ void k_copy_tail(float* __restrict__ dst) {
    int i = blockIdx.x * blockDim.x + threadIdx.x;
    if (i < Bc*TYc*2*Hc) dst[i] = g_outhid[i];
}

// ---------------- launch ----------------
extern "C" void kernel_launch(void* const* d_in, const int* in_sizes, int n_in,
                              void* d_out, int out_size) {
    (void)in_sizes; (void)n_in;
    const int*   x      = (const int*)  d_in[0];
    const float* xmask  = (const float*)d_in[1];
    const int*   y      = (const int*)  d_in[2];
    const float* embed  = (const float*)d_in[3];
    const float* w_ih_f = (const float*)d_in[4];
    const float* w_hh_f = (const float*)d_in[5];
    const float* b_ih_f = (const float*)d_in[6];
    const float* b_hh_f = (const float*)d_in[7];
    const float* w_ih_b = (const float*)d_in[8];
    const float* w_hh_b = (const float*)d_in[9];
    const float* b_ih_b = (const float*)d_in[10];
    const float* b_hh_b = (const float*)d_in[11];
    const float* w_ih_d = (const float*)d_in[12];
    const float* w_hh_d = (const float*)d_in[13];
    const float* b_ih_d = (const float*)d_in[14];
    const float* b_hh_d = (const float*)d_in[15];
    const float* W_out  = (const float*)d_in[16];
    const float* b_out  = (const float*)d_in[17];
    float* out = (float*)d_out;

    void *p_xembh, *p_xbembh, *p_yembh, *p_pref, *p_preb, *p_decpre, *p_outhid, *p_outhidh, *p_xback;
    void *p_wf, *p_wb, *p_wd, *p_Wo;
    cudaGetSymbolAddress(&p_xembh,  g_xembh);
    cudaGetSymbolAddress(&p_xbembh, g_xbembh);
    cudaGetSymbolAddress(&p_yembh,  g_yembh);
    cudaGetSymbolAddress(&p_pref,   g_encpre_f);
    cudaGetSymbolAddress(&p_preb,   g_encpre_b);
    cudaGetSymbolAddress(&p_decpre, g_decpre);
    cudaGetSymbolAddress(&p_outhid, g_outhid);
    cudaGetSymbolAddress(&p_outhidh,g_outhidh);
    cudaGetSymbolAddress(&p_xback,  g_xback);
    cudaGetSymbolAddress(&p_wf,     g_wihf_h);
    cudaGetSymbolAddress(&p_wb,     g_wihb_h);
    cudaGetSymbolAddress(&p_wd,     g_wihd_h);
    cudaGetSymbolAddress(&p_Wo,     g_Wouth);

    const int ENC_SMEM = (256*16 + 256*33 + 16*33) * 4;   //  52,288 B
    const int DEC_SMEM = (512*16 + 512*33 + 16*33) * 4;   // 102,464 B
    static bool attr_done = false;
    if (!attr_done) {
        cudaFuncSetAttribute(k_enc_scan, cudaFuncAttributeMaxDynamicSharedMemorySize, ENC_SMEM);
        cudaFuncSetAttribute(k_dec_scan, cudaFuncAttributeMaxDynamicSharedMemorySize, DEC_SMEM);
        attr_done = true;
    }

    k_init<<<128, 256>>>();
    k_xback<<<1, 32>>>(x, xmask);

    // weight conversions (fp32 -> fp16)
    k_f2h<<<(4*HHc*Ec/4 + 255)/256, 256>>>(w_ih_f, (__half*)p_wf, 4*HHc*Ec/4);
    k_f2h<<<(4*HHc*Ec/4 + 255)/256, 256>>>(w_ih_b, (__half*)p_wb, 4*HHc*Ec/4);
    k_f2h<<<(4*Hc*Ec/4  + 255)/256, 256>>>(w_ih_d, (__half*)p_wd, 4*Hc*Ec/4);
    k_f2h<<<(Vc*2*Hc/4  + 255)/256, 256>>>(W_out,  (__half*)p_Wo, Vc*2*Hc/4);

    k_gather_h<<<Bc*Tc, 128>>>(x, embed, (__half*)p_xembh);
    k_gather_h<<<Bc*Tc, 128>>>((const int*)p_xback, embed, (__half*)p_xbembh);
    k_gather_h<<<Bc*TYc, 128>>>(y, embed, (__half*)p_yembh);

    // time-batched input-side GEMMs (fp16 mma + ldmatrix), fold both biases
    k_hmma<<<dim3((Bc*Tc)/128, (4*HHc)/128), 256>>>(
        (const __half*)p_xembh,  (const __half*)p_wf, b_ih_f, b_hh_f, (float*)p_pref,   Bc*Tc,  4*HHc, Ec);
    k_hmma<<<dim3((Bc*Tc)/128, (4*HHc)/128), 256>>>(
        (const __half*)p_xbembh, (const __half*)p_wb, b_ih_b, b_hh_b, (float*)p_preb,   Bc*Tc,  4*HHc, Ec);
    k_hmma<<<dim3((Bc*TYc)/128, (4*Hc)/128), 256>>>(
        (const __half*)p_yembh,  (const __half*)p_wd, b_ih_d, b_hh_d, (float*)p_decpre, Bc*TYc, 4*Hc,  Ec);

    // persistent scans (software grid barriers; 128 blocks <= SM count)
    k_enc_scan<<<128, 256, ENC_SMEM>>>(w_hh_f, w_hh_b);
    k_dec_scan<<<128, 256, DEC_SMEM>>>(w_hh_d);

    // attention, fully parallel over (b, ty); writes fp32 + fp16 outhid
    k_attn<<<dim3(Bc, TYc), 256>>>();

    // projection + log_softmax
    k_hmma<<<dim3((Bc*TYc)/128, Vc/128), 256>>>(
        (const __half*)p_outhidh, (const __half*)p_Wo, b_out, nullptr, out, Bc*TYc, Vc, 2*Hc);
    k_logsoftmax<<<Bc*TYc, 256>>>(out);

    long long need = (long long)Bc*TYc*Vc + (long long)Bc*TYc*2*Hc;
    if ((long long)out_size >= need)
        k_copy_tail<<<(Bc*TYc*2*Hc + 255)/256, 256>>>(out + (size_t)Bc*TYc*Vc);
}